// round 1
// baseline (speedup 1.0000x reference)
#include <cuda_runtime.h>
#include <math.h>

// ---------------- problem dims ----------------
constexpr int Bb = 32, Cc = 512, Hh = 24, Ww = 24;
constexpr int Ll = Hh * Ww;          // 576
constexpr int Dd = 1024, Kk = 4, Nst = 4, Rr = 32, MH = 2048;
constexpr int BL = Bb * Ll;          // 18432
constexpr int XDBL = Rr + 2 * Nst;   // 40

// ---------------- scratch (single device global, no allocs) ----------------
constexpr size_t OFF_XT     = 0;
constexpr size_t OFF_H      = OFF_XT     + (size_t)BL * Cc;
constexpr size_t OFF_XZ     = OFF_H      + (size_t)BL * Cc;
constexpr size_t OFF_XC     = OFF_XZ     + (size_t)BL * 2 * Dd;
constexpr size_t OFF_XS     = OFF_XC     + (size_t)BL * Dd;
constexpr size_t OFF_XDBL   = OFF_XS     + (size_t)Kk * BL * Dd;
constexpr size_t OFF_DTS    = OFF_XDBL   + (size_t)Kk * BL * XDBL;
constexpr size_t OFF_YS     = OFF_DTS    + (size_t)Kk * BL * Dd;
constexpr size_t OFF_YG     = OFF_YS     + (size_t)Kk * BL * Dd;
constexpr size_t OFF_XRES   = OFF_YG     + (size_t)BL * Dd;
constexpr size_t OFF_M1     = OFF_XRES   + (size_t)BL * Cc;
constexpr size_t OFF_MH     = OFF_M1     + (size_t)BL * Cc;
constexpr size_t OFF_XFIN   = OFF_MH     + (size_t)BL * MH;
constexpr size_t OFF_DTWT   = OFF_XFIN   + (size_t)BL * Cc;
constexpr size_t OFF_CONVWT = OFF_DTWT   + (size_t)Kk * Rr * Dd;
constexpr size_t TOT        = OFF_CONVWT + (size_t)9 * Dd;

__device__ float g_buf[TOT];

#define BUF(off) (g_buf + (off))

// ---------------- kernel 1: xt = p2t(x1)+p2t(x2)+p2t(x3) (transpose-sum) ----------------
__global__ void k_fuse(const float* __restrict__ x1, const float* __restrict__ x2,
                       const float* __restrict__ x3) {
    __shared__ float t[32][33];
    const int b  = blockIdx.z;
    const int c0 = blockIdx.x * 32;
    const int l0 = blockIdx.y * 32;
    const int tx = threadIdx.x, ty = threadIdx.y;  // 32 x 8
    const size_t base = (size_t)b * Cc * Ll;
    for (int i = ty; i < 32; i += 8) {
        const size_t idx = base + (size_t)(c0 + i) * Ll + (l0 + tx);
        t[i][tx] = x1[idx] + x2[idx] + x3[idx];
    }
    __syncthreads();
    float* xt = BUF(OFF_XT);
    for (int i = ty; i < 32; i += 8) {
        xt[((size_t)b * Ll + (l0 + i)) * Cc + (c0 + tx)] = t[tx][i];
    }
}

// ---------------- generic row LayerNorm ----------------
template <int WIDTH>
__global__ void k_ln(size_t offIn, const float* __restrict__ w, const float* __restrict__ bvec,
                     size_t offOut) {
    constexpr int T = 256;
    __shared__ float red[T];
    const size_t row = blockIdx.x;
    const float* x = BUF(offIn) + row * WIDTH;
    float* out = BUF(offOut) + row * WIDTH;
    const int tid = threadIdx.x;

    float s = 0.f;
    for (int i = tid; i < WIDTH; i += T) s += x[i];
    red[tid] = s; __syncthreads();
    for (int o = T / 2; o > 0; o >>= 1) { if (tid < o) red[tid] += red[tid + o]; __syncthreads(); }
    const float mu = red[0] * (1.f / WIDTH);
    __syncthreads();

    float s2 = 0.f;
    for (int i = tid; i < WIDTH; i += T) { float dv = x[i] - mu; s2 += dv * dv; }
    red[tid] = s2; __syncthreads();
    for (int o = T / 2; o > 0; o >>= 1) { if (tid < o) red[tid] += red[tid + o]; __syncthreads(); }
    const float inv = rsqrtf(red[0] * (1.f / WIDTH) + 1e-5f);

    for (int i = tid; i < WIDTH; i += T) out[i] = (x[i] - mu) * inv * w[i] + bvec[i];
}

// ---------------- SGEMM (NT: A[M,K] row-major, Bw[N,K] row-major), C = A*Bw^T ----------------
// EPI: 0 = +bias ; 1 = +bias + residual ; 2 = gelu(+bias)
template <int BM, int BN, int BK, int TM, int TN, int EPI>
__global__ __launch_bounds__((BM / TM) * (BN / TN))
void k_gemm(size_t offA, const float* __restrict__ Bw, const float* __restrict__ bias,
            size_t offRes, size_t offC, int M, int Nn, int Kd) {
    constexpr int NT = (BM / TM) * (BN / TN);
    __shared__ float As[BK][BM];
    __shared__ float Bs[BK][BN];
    const float* A = BUF(offA);
    const float* Res = BUF(offRes);
    float* Cmat = BUF(offC);

    const int tid = threadIdx.x;
    const int bm = blockIdx.x * BM;
    const int bn = blockIdx.y * BN;
    const int tx = tid % (BN / TN);
    const int ty = tid / (BN / TN);

    float acc[TM][TN];
#pragma unroll
    for (int i = 0; i < TM; i++)
#pragma unroll
        for (int j = 0; j < TN; j++) acc[i][j] = 0.f;

    for (int k0 = 0; k0 < Kd; k0 += BK) {
        constexpr int AV = BM * BK / 4;
        for (int i = tid; i < AV; i += NT) {
            const int row = i / (BK / 4), kk = (i % (BK / 4)) * 4;
            const float4 v = *reinterpret_cast<const float4*>(&A[(size_t)(bm + row) * Kd + k0 + kk]);
            As[kk][row] = v.x; As[kk + 1][row] = v.y; As[kk + 2][row] = v.z; As[kk + 3][row] = v.w;
        }
        constexpr int BV = BN * BK / 4;
        for (int i = tid; i < BV; i += NT) {
            const int row = i / (BK / 4), kk = (i % (BK / 4)) * 4;
            float4 v = make_float4(0.f, 0.f, 0.f, 0.f);
            if (bn + row < Nn)
                v = *reinterpret_cast<const float4*>(&Bw[(size_t)(bn + row) * Kd + k0 + kk]);
            Bs[kk][row] = v.x; Bs[kk + 1][row] = v.y; Bs[kk + 2][row] = v.z; Bs[kk + 3][row] = v.w;
        }
        __syncthreads();
#pragma unroll
        for (int k = 0; k < BK; k++) {
            float a[TM], b[TN];
#pragma unroll
            for (int i = 0; i < TM; i++) a[i] = As[k][ty * TM + i];
#pragma unroll
            for (int j = 0; j < TN; j++) b[j] = Bs[k][tx * TN + j];
#pragma unroll
            for (int i = 0; i < TM; i++)
#pragma unroll
                for (int j = 0; j < TN; j++) acc[i][j] += a[i] * b[j];
        }
        __syncthreads();
    }

#pragma unroll
    for (int i = 0; i < TM; i++) {
        const int m = bm + ty * TM + i;
#pragma unroll
        for (int j = 0; j < TN; j++) {
            const int n = bn + tx * TN + j;
            if (n >= Nn) continue;
            float v = acc[i][j];
            if (bias) v += bias[n];
            if (EPI == 1) v += Res[(size_t)m * Nn + n];
            if (EPI == 2) {
                const float xg = v;
                v = 0.5f * xg * (1.f + tanhf(0.7978845608028654f * (xg + 0.044715f * xg * xg * xg)));
            }
            Cmat[(size_t)m * Nn + n] = v;
        }
    }
}

// ---------------- prep: transpose dt_w (K,D,R)->(K,R,D), conv_w (D,9)->(9,D) ----------------
__global__ void k_prep(const float* __restrict__ dt_w, const float* __restrict__ conv_w) {
    const int i = blockIdx.x * 256 + threadIdx.x;
    if (i < Kk * Rr * Dd) {
        const int k = i / (Rr * Dd);
        const int rem = i % (Rr * Dd);
        const int r = rem / Dd, d = rem % Dd;
        BUF(OFF_DTWT)[i] = dt_w[((size_t)k * Dd + d) * Rr + r];
    }
    if (i < 9 * Dd) {
        const int j = i / Dd, d = i % Dd;
        BUF(OFF_CONVWT)[i] = conv_w[(size_t)d * 9 + j];
    }
}

// ---------------- depthwise 3x3 conv + SiLU: xz[:, :D] -> xc (B,L,D) ----------------
__global__ void k_conv(const float* __restrict__ conv_b) {
    const int bl = blockIdx.x;
    const int d = blockIdx.y * 256 + threadIdx.x;
    const int b = bl / Ll, l = bl % Ll;
    const int h = l / Ww, w = l % Ww;
    const float* xz = BUF(OFF_XZ);
    const float* cw = BUF(OFF_CONVWT);
    float acc = 0.f;
#pragma unroll
    for (int kh = -1; kh <= 1; kh++) {
        const int hh = h + kh;
        if (hh < 0 || hh >= Hh) continue;
#pragma unroll
        for (int kw = -1; kw <= 1; kw++) {
            const int ww2 = w + kw;
            if (ww2 < 0 || ww2 >= Ww) continue;
            acc += xz[((size_t)(b * Ll + hh * Ww + ww2)) * 2 * Dd + d] *
                   cw[(size_t)((kh + 1) * 3 + (kw + 1)) * Dd + d];
        }
    }
    acc += conv_b[d];
    BUF(OFF_XC)[(size_t)bl * Dd + d] = acc / (1.f + __expf(-acc));  // silu
}

// ---------------- cross-scan: xc (B,L,D) -> xs (K,B,L,D) ----------------
__global__ void k_xscan() {
    const int bl = blockIdx.x;
    const int d = blockIdx.y * 256 + threadIdx.x;
    const int b = bl / Ll, l = bl % Ll;
    const float* xc = BUF(OFF_XC);
    float* xs = BUF(OFF_XS);
    const float v0 = xc[(size_t)bl * Dd + d];
    const int l1 = (l % Hh) * Ww + (l / Hh);   // transposed read position
    const float v1 = xc[((size_t)b * Ll + l1) * Dd + d];
    xs[(((size_t)(0 * Bb + b)) * Ll + l) * Dd + d] = v0;
    xs[(((size_t)(1 * Bb + b)) * Ll + l) * Dd + d] = v1;
    xs[(((size_t)(2 * Bb + b)) * Ll + (Ll - 1 - l)) * Dd + d] = v0;
    xs[(((size_t)(3 * Bb + b)) * Ll + (Ll - 1 - l)) * Dd + d] = v1;
}

// ---------------- dts = softplus(x_dbl[:, :R] @ dt_w^T + dt_b) ----------------
__global__ void k_dt(const float* __restrict__ dt_b) {
    constexpr int LT = 8;
    __shared__ float s[LT][Rr];
    const int blk = blockIdx.x;
    const int lt = blk % (Ll / LT);
    const int rem = blk / (Ll / LT);
    const int b = rem % Bb;
    const int k = rem / Bb;
    const int l0 = lt * LT;
    const int tid = threadIdx.x;

    {   // 8 * 32 = 256 loads, one per thread
        const int i = tid / Rr, r = tid % Rr;
        s[i][r] = BUF(OFF_XDBL)[(((size_t)k * Bb + b) * Ll + l0 + i) * XDBL + r];
    }
    __syncthreads();

    const float* wT = BUF(OFF_DTWT);
    float* dts = BUF(OFF_DTS);
    for (int dc = 0; dc < Dd / 256; dc++) {
        const int d = dc * 256 + tid;
        const float bias = dt_b[k * Dd + d];
        float acc[LT];
#pragma unroll
        for (int i = 0; i < LT; i++) acc[i] = bias;
        for (int r = 0; r < Rr; r++) {
            const float wv = wT[((size_t)k * Rr + r) * Dd + d];
#pragma unroll
            for (int i = 0; i < LT; i++) acc[i] += s[i][r] * wv;
        }
#pragma unroll
        for (int i = 0; i < LT; i++) {
            const float x = acc[i];
            const float sp = (x > 20.f) ? x : log1pf(__expf(x));
            dts[(((size_t)k * Bb + b) * Ll + l0 + i) * Dd + d] = sp;
        }
    }
}

// ---------------- selective scan over L (thread per (k,b,d)) ----------------
__global__ void k_scan(const float* __restrict__ A_logs, const float* __restrict__ Ds) {
    const int blk = blockIdx.x;            // ((k*Bb + b) * 4 + dc)
    const int dc = blk & 3;
    const int kb = blk >> 2;
    const int b = kb % Bb;
    const int k = kb / Bb;
    const int d = dc * 256 + threadIdx.x;

    float Aa[Nst];
#pragma unroll
    for (int n = 0; n < Nst; n++) Aa[n] = -__expf(A_logs[((size_t)k * Dd + d) * Nst + n]);
    const float Dv = Ds[k * Dd + d];

    const float* xs = BUF(OFF_XS);
    const float* dts = BUF(OFF_DTS);
    const float* xdbl = BUF(OFF_XDBL);
    float* ys = BUF(OFF_YS);

    const size_t ubase = ((size_t)k * Bb + b) * Ll * Dd + d;
    const size_t bcbase = ((size_t)k * Bb + b) * Ll * XDBL;

    float hst[Nst] = {0.f, 0.f, 0.f, 0.f};
    for (int l = 0; l < Ll; l++) {
        const float u = xs[ubase + (size_t)l * Dd];
        const float dt = dts[ubase + (size_t)l * Dd];
        const float* bc = xdbl + bcbase + (size_t)l * XDBL + Rr;
        const float du = dt * u;
        float y = 0.f;
#pragma unroll
        for (int n = 0; n < Nst; n++) {
            const float dA = __expf(dt * Aa[n]);
            hst[n] = hst[n] * dA + du * bc[n];
            y += hst[n] * bc[Nst + n];
        }
        ys[ubase + (size_t)l * Dd] = y + Dv * u;
    }
}

// ---------------- cross-merge + out_norm LN + SiLU(z) gate -> yg (B,L,D) ----------------
__global__ void k_merge(const float* __restrict__ onw, const float* __restrict__ onb) {
    constexpr int T = 256;
    __shared__ float bufr[Dd];
    __shared__ float red[T];
    const int bl = blockIdx.x;
    const int b = bl / Ll, l = bl % Ll;
    const int h = l / Ww, w = l % Ww;
    const int lt = w * Hh + h;
    const int tid = threadIdx.x;
    const float* ys = BUF(OFF_YS);

    const size_t r0 = (((size_t)(0 * Bb + b)) * Ll + l) * Dd;
    const size_t r1 = (((size_t)(1 * Bb + b)) * Ll + lt) * Dd;
    const size_t r2 = (((size_t)(2 * Bb + b)) * Ll + (Ll - 1 - l)) * Dd;
    const size_t r3 = (((size_t)(3 * Bb + b)) * Ll + (Ll - 1 - lt)) * Dd;

    float s = 0.f;
#pragma unroll
    for (int it = 0; it < Dd / T; it++) {
        const int d = tid + it * T;
        const float v = ys[r0 + d] + ys[r1 + d] + ys[r2 + d] + ys[r3 + d];
        bufr[d] = v; s += v;
    }
    red[tid] = s; __syncthreads();
    for (int o = T / 2; o > 0; o >>= 1) { if (tid < o) red[tid] += red[tid + o]; __syncthreads(); }
    const float mu = red[0] * (1.f / Dd);
    __syncthreads();

    float s2 = 0.f;
#pragma unroll
    for (int it = 0; it < Dd / T; it++) {
        const int d = tid + it * T;
        const float dv = bufr[d] - mu; s2 += dv * dv;
    }
    red[tid] = s2; __syncthreads();
    for (int o = T / 2; o > 0; o >>= 1) { if (tid < o) red[tid] += red[tid + o]; __syncthreads(); }
    const float inv = rsqrtf(red[0] * (1.f / Dd) + 1e-5f);

    const float* xz = BUF(OFF_XZ);
    float* yg = BUF(OFF_YG);
#pragma unroll
    for (int it = 0; it < Dd / T; it++) {
        const int d = tid + it * T;
        const float zv = xz[(size_t)bl * 2 * Dd + Dd + d];
        const float g = zv / (1.f + __expf(-zv));
        yg[(size_t)bl * Dd + d] = ((bufr[d] - mu) * inv * onw[d] + onb[d]) * g;
    }
}

// ---------------- final token2patch transpose ----------------
__global__ void k_out(float* __restrict__ out) {
    __shared__ float t[32][33];
    const int b = blockIdx.z;
    const int l0 = blockIdx.x * 32;
    const int c0 = blockIdx.y * 32;
    const int tx = threadIdx.x, ty = threadIdx.y;
    const float* xf = BUF(OFF_XFIN);
    for (int i = ty; i < 32; i += 8)
        t[i][tx] = xf[((size_t)b * Ll + (l0 + i)) * Cc + (c0 + tx)];
    __syncthreads();
    for (int i = ty; i < 32; i += 8)
        out[((size_t)b * Cc + (c0 + i)) * Ll + (l0 + tx)] = t[tx][i];
}

// ---------------- launch ----------------
extern "C" void kernel_launch(void* const* d_in, const int* in_sizes, int n_in,
                              void* d_out, int out_size) {
    const float* x1        = (const float*)d_in[0];
    const float* x2        = (const float*)d_in[1];
    const float* x3        = (const float*)d_in[2];
    const float* ln1_w     = (const float*)d_in[3];
    const float* ln1_b     = (const float*)d_in[4];
    const float* in_proj_w = (const float*)d_in[5];
    const float* in_proj_b = (const float*)d_in[6];
    const float* conv_w    = (const float*)d_in[7];
    const float* conv_b    = (const float*)d_in[8];
    const float* x_proj_w  = (const float*)d_in[9];
    const float* dt_w      = (const float*)d_in[10];
    const float* dt_b      = (const float*)d_in[11];
    const float* A_logs    = (const float*)d_in[12];
    const float* Ds        = (const float*)d_in[13];
    const float* out_norm_w= (const float*)d_in[14];
    const float* out_norm_b= (const float*)d_in[15];
    const float* out_proj_w= (const float*)d_in[16];
    const float* out_proj_b= (const float*)d_in[17];
    const float* ln2_w     = (const float*)d_in[18];
    const float* ln2_b     = (const float*)d_in[19];
    const float* fc1_w     = (const float*)d_in[20];
    const float* fc1_b     = (const float*)d_in[21];
    const float* fc2_w     = (const float*)d_in[22];
    const float* fc2_b     = (const float*)d_in[23];
    float* out = (float*)d_out;

    // 1. fuse + transpose -> xt (B,L,C)
    k_fuse<<<dim3(Cc / 32, Ll / 32, Bb), dim3(32, 8)>>>(x1, x2, x3);
    // 2. LN1 -> h
    k_ln<Cc><<<BL, 256>>>(OFF_XT, ln1_w, ln1_b, OFF_H);
    // 3. in_proj GEMM: xz = h @ W^T + b   (BL x 2048, K=512)
    k_gemm<128, 128, 16, 8, 8, 0><<<dim3(BL / 128, 2 * Dd / 128), 256>>>(
        OFF_H, in_proj_w, in_proj_b, 0, OFF_XZ, BL, 2 * Dd, Cc);
    // 4. weight transposes
    k_prep<<<(Kk * Rr * Dd + 255) / 256, 256>>>(dt_w, conv_w);
    // 5. depthwise conv + silu -> xc
    k_conv<<<dim3(BL, Dd / 256), 256>>>(conv_b);
    // 6. cross-scan -> xs (K,B,L,D)
    k_xscan<<<dim3(BL, Dd / 256), 256>>>();
    // 7. x_proj per direction: x_dbl[k] = xs[k] @ Wk^T   (BL x 40, K=1024)
    for (int k = 0; k < Kk; k++) {
        k_gemm<128, 64, 16, 8, 4, 0><<<dim3(BL / 128, 1), 256>>>(
            OFF_XS + (size_t)k * BL * Dd, x_proj_w + (size_t)k * XDBL * Dd, nullptr,
            0, OFF_XDBL + (size_t)k * BL * XDBL, BL, XDBL, Dd);
    }
    // 8. dt projection + softplus -> dts
    k_dt<<<Kk * Bb * (Ll / 8), 256>>>(dt_b);
    // 9. selective scan -> ys
    k_scan<<<Kk * Bb * 4, 256>>>(A_logs, Ds);
    // 10. merge + out_norm LN + gate -> yg
    k_merge<<<BL, 256>>>(out_norm_w, out_norm_b);
    // 11. out_proj GEMM + residual(xt) -> xres (BL x 512, K=1024)
    k_gemm<128, 128, 16, 8, 8, 1><<<dim3(BL / 128, Cc / 128), 256>>>(
        OFF_YG, out_proj_w, out_proj_b, OFF_XT, OFF_XRES, BL, Cc, Dd);
    // 12. LN2 -> m1
    k_ln<Cc><<<BL, 256>>>(OFF_XRES, ln2_w, ln2_b, OFF_M1);
    // 13. fc1 GEMM + gelu -> mh (BL x 2048, K=512)
    k_gemm<128, 128, 16, 8, 8, 2><<<dim3(BL / 128, MH / 128), 256>>>(
        OFF_M1, fc1_w, fc1_b, 0, OFF_MH, BL, MH, Cc);
    // 14. fc2 GEMM + bias + residual(xres) -> xfin (BL x 512, K=2048)
    k_gemm<128, 128, 16, 8, 8, 1><<<dim3(BL / 128, Cc / 128), 256>>>(
        OFF_MH, fc2_w, fc2_b, OFF_XRES, OFF_XFIN, BL, Cc, MH);
    // 15. token2patch transpose -> out (B,C,H,W)
    k_out<<<dim3(Ll / 32, Cc / 32, Bb), dim3(32, 8)>>>(out);
}

// round 3
// speedup vs baseline: 1.7083x; 1.7083x over previous
#include <cuda_runtime.h>
#include <cuda_bf16.h>
#include <math.h>
#include <stdint.h>

// ---------------- problem dims ----------------
constexpr int Bb = 32, Cc = 512, Hh = 24, Ww = 24;
constexpr int Ll = Hh * Ww;          // 576
constexpr int Dd = 1024, Kk = 4, Nst = 4, Rr = 32, MH = 2048;
constexpr int BL = Bb * Ll;          // 18432
constexpr int XDBL = Rr + 2 * Nst;   // 40

// ---------------- fp32 scratch ----------------
constexpr size_t OFF_XT     = 0;
constexpr size_t OFF_XZ     = OFF_XT     + (size_t)BL * Cc;
constexpr size_t OFF_XC     = OFF_XZ     + (size_t)BL * 2 * Dd;
constexpr size_t OFF_XS     = OFF_XC     + (size_t)BL * Dd;
constexpr size_t OFF_XDBL   = OFF_XS     + (size_t)Kk * BL * Dd;
constexpr size_t OFF_DTS    = OFF_XDBL   + (size_t)Kk * BL * XDBL;
constexpr size_t OFF_YS     = OFF_DTS    + (size_t)Kk * BL * Dd;
constexpr size_t OFF_XRES   = OFF_YS     + (size_t)Kk * BL * Dd;
constexpr size_t OFF_XFIN   = OFF_XRES   + (size_t)BL * Cc;
constexpr size_t OFF_DTWT   = OFF_XFIN   + (size_t)BL * Cc;
constexpr size_t OFF_CONVWT = OFF_DTWT   + (size_t)Kk * Rr * Dd;
constexpr size_t TOTF       = OFF_CONVWT + (size_t)9 * Dd;

__device__ __align__(128) float g_buf[TOTF];
#define BUF(off) (g_buf + (off))

// ---------------- bf16 scratch (hi/lo split operands) ----------------
constexpr size_t BH_H_HI   = 0;
constexpr size_t BH_H_LO   = BH_H_HI   + (size_t)BL * Cc;
constexpr size_t BH_YG_HI  = BH_H_LO   + (size_t)BL * Cc;
constexpr size_t BH_YG_LO  = BH_YG_HI  + (size_t)BL * Dd;
constexpr size_t BH_M1_HI  = BH_YG_LO  + (size_t)BL * Dd;
constexpr size_t BH_M1_LO  = BH_M1_HI  + (size_t)BL * Cc;
constexpr size_t BH_MH_HI  = BH_M1_LO  + (size_t)BL * Cc;
constexpr size_t BH_MH_LO  = BH_MH_HI  + (size_t)BL * MH;
constexpr size_t BH_WIP_HI = BH_MH_LO  + (size_t)BL * MH;
constexpr size_t BH_WIP_LO = BH_WIP_HI + (size_t)2 * Dd * Cc;
constexpr size_t BH_WOP_HI = BH_WIP_LO + (size_t)2 * Dd * Cc;
constexpr size_t BH_WOP_LO = BH_WOP_HI + (size_t)Cc * Dd;
constexpr size_t BH_WF1_HI = BH_WOP_LO + (size_t)Cc * Dd;
constexpr size_t BH_WF1_LO = BH_WF1_HI + (size_t)MH * Cc;
constexpr size_t BH_WF2_HI = BH_WF1_LO + (size_t)MH * Cc;
constexpr size_t BH_WF2_LO = BH_WF2_HI + (size_t)Cc * MH;
constexpr size_t TOTB      = BH_WF2_LO + (size_t)Cc * MH;

__device__ __align__(128) __nv_bfloat16 g_bh[TOTB];

// ---------------- mma.sync helpers ----------------
__device__ __forceinline__ uint32_t s2u(const void* p) {
    uint32_t a;
    asm("{ .reg .u64 t; cvta.to.shared.u64 t, %1; cvt.u32.u64 %0, t; }" : "=r"(a) : "l"(p));
    return a;
}
__device__ __forceinline__ void ldm_x4(uint32_t* d, uint32_t addr) {
    asm volatile("ldmatrix.sync.aligned.m8n8.x4.shared.b16 {%0,%1,%2,%3}, [%4];"
                 : "=r"(d[0]), "=r"(d[1]), "=r"(d[2]), "=r"(d[3]) : "r"(addr));
}
__device__ __forceinline__ void ldm_x2(uint32_t* d, uint32_t addr) {
    asm volatile("ldmatrix.sync.aligned.m8n8.x2.shared.b16 {%0,%1}, [%2];"
                 : "=r"(d[0]), "=r"(d[1]) : "r"(addr));
}
__device__ __forceinline__ void mma_bf16(float* c, const uint32_t* a, const uint32_t* b) {
    asm volatile(
        "mma.sync.aligned.m16n8k16.row.col.f32.bf16.bf16.f32 "
        "{%0,%1,%2,%3}, {%4,%5,%6,%7}, {%8,%9}, {%0,%1,%2,%3};"
        : "+f"(c[0]), "+f"(c[1]), "+f"(c[2]), "+f"(c[3])
        : "r"(a[0]), "r"(a[1]), "r"(a[2]), "r"(a[3]), "r"(b[0]), "r"(b[1]));
}

__device__ __forceinline__ float gelu_tanh(float x) {
    return 0.5f * x * (1.f + tanhf(0.7978845608028654f * (x + 0.044715f * x * x * x)));
}

// ---------------- split-bf16 tensor-core GEMM: C[M,N] = A[M,K] @ B[N,K]^T ----------------
// 3 passes: A_hi*B_hi + A_lo*B_hi + A_hi*B_lo, fp32 register accumulation.
// EPI 0: +bias -> fp32. EPI 1: +bias +res -> fp32. EPI 2: gelu(+bias) -> bf16 hi/lo.
template <int EPI>
__global__ __launch_bounds__(256)
void k_gemm_mma(const __nv_bfloat16* __restrict__ Ahi, const __nv_bfloat16* __restrict__ Alo,
                const __nv_bfloat16* __restrict__ Bhi, const __nv_bfloat16* __restrict__ Blo,
                const float* __restrict__ bias, const float* __restrict__ res,
                float* __restrict__ outF,
                __nv_bfloat16* __restrict__ outHi, __nv_bfloat16* __restrict__ outLo,
                int Nn, int Kd) {
    __shared__ __align__(128) char smA[2][8192];   // 128 rows x 64B (BK=32 bf16), swizzled
    __shared__ __align__(128) char smB[2][8192];

    const int tid = threadIdx.x;
    const int lane = tid & 31, wid = tid >> 5;
    const int wm = wid & 1, wn = wid >> 1;      // 2 x 4 warp grid
    const int bm = blockIdx.x * 128, bn = blockIdx.y * 128;

    const int nk = Kd >> 5;        // K chunks of 32
    const int T = 3 * nk;          // 3 split passes
    const __nv_bfloat16* pa[3] = {Ahi, Alo, Ahi};
    const __nv_bfloat16* pb[3] = {Bhi, Bhi, Blo};

    // per-thread global->smem coords (two 16B chunks per tile)
    const int r0s = tid >> 2, c0s = tid & 3;
    const int r1s = r0s + 64, c1s = c0s;
    const uint32_t sw0 = r0s * 64 + (((c0s + (r0s >> 1)) & 3) << 4);
    const uint32_t sw1 = r1s * 64 + (((c1s + (r1s >> 1)) & 3) << 4);

    float acc[4][4][4];
#pragma unroll
    for (int i = 0; i < 4; i++)
#pragma unroll
        for (int j = 0; j < 4; j++)
#pragma unroll
            for (int q = 0; q < 4; q++) acc[i][j][q] = 0.f;

    // prologue: load chunk 0 into stage 0
    {
        const __nv_bfloat16* A = pa[0];
        const __nv_bfloat16* B = pb[0];
        const uint4 a0 = *(const uint4*)(A + (size_t)(bm + r0s) * Kd + c0s * 8);
        const uint4 a1 = *(const uint4*)(A + (size_t)(bm + r1s) * Kd + c1s * 8);
        const uint4 b0 = *(const uint4*)(B + (size_t)(bn + r0s) * Kd + c0s * 8);
        const uint4 b1 = *(const uint4*)(B + (size_t)(bn + r1s) * Kd + c1s * 8);
        *(uint4*)(smA[0] + sw0) = a0;
        *(uint4*)(smA[0] + sw1) = a1;
        *(uint4*)(smB[0] + sw0) = b0;
        *(uint4*)(smB[0] + sw1) = b1;
    }
    __syncthreads();

    for (int it = 0; it < T; it++) {
        const int s = it & 1;
        const bool pf = (it + 1 < T);
        uint4 na0, na1, nb0, nb1;
        if (pf) {
            const int p = (it + 1) / nk;
            const int kc = ((it + 1) - p * nk) * 32;
            const __nv_bfloat16* A = pa[p];
            const __nv_bfloat16* B = pb[p];
            na0 = *(const uint4*)(A + (size_t)(bm + r0s) * Kd + kc + c0s * 8);
            na1 = *(const uint4*)(A + (size_t)(bm + r1s) * Kd + kc + c1s * 8);
            nb0 = *(const uint4*)(B + (size_t)(bn + r0s) * Kd + kc + c0s * 8);
            nb1 = *(const uint4*)(B + (size_t)(bn + r1s) * Kd + kc + c1s * 8);
        }
        const uint32_t aBase = s2u(smA[s]);
        const uint32_t bBase = s2u(smB[s]);
#pragma unroll
        for (int s16 = 0; s16 < 2; s16++) {
            uint32_t af[4][4], bfr[4][2];
#pragma unroll
            for (int mi = 0; mi < 4; mi++) {
                const int r = wm * 64 + mi * 16 + (lane & 15);
                const int c = 2 * s16 + (lane >> 4);
                ldm_x4(af[mi], aBase + r * 64 + (((c + (r >> 1)) & 3) << 4));
            }
#pragma unroll
            for (int ni = 0; ni < 4; ni++) {
                const int i = lane & 15;
                const int r = wn * 32 + ni * 8 + (i & 7);
                const int c = 2 * s16 + (i >> 3);
                ldm_x2(bfr[ni], bBase + r * 64 + (((c + (r >> 1)) & 3) << 4));
            }
#pragma unroll
            for (int mi = 0; mi < 4; mi++)
#pragma unroll
                for (int ni = 0; ni < 4; ni++)
                    mma_bf16(acc[mi][ni], af[mi], bfr[ni]);
        }
        if (pf) {
            const int s2_ = (it + 1) & 1;
            *(uint4*)(smA[s2_] + sw0) = na0;
            *(uint4*)(smA[s2_] + sw1) = na1;
            *(uint4*)(smB[s2_] + sw0) = nb0;
            *(uint4*)(smB[s2_] + sw1) = nb1;
            __syncthreads();
        }
    }

    // epilogue
#pragma unroll
    for (int mi = 0; mi < 4; mi++) {
#pragma unroll
        for (int ni = 0; ni < 4; ni++) {
            const int n = bn + wn * 32 + ni * 8 + (lane & 3) * 2;
            const float b0v = bias[n], b1v = bias[n + 1];
#pragma unroll
            for (int h = 0; h < 2; h++) {
                const int m = bm + wm * 64 + mi * 16 + (lane >> 2) + h * 8;
                float v0 = acc[mi][ni][h * 2 + 0] + b0v;
                float v1 = acc[mi][ni][h * 2 + 1] + b1v;
                if (EPI == 1) {
                    const float2 rv = *(const float2*)(res + (size_t)m * Nn + n);
                    v0 += rv.x; v1 += rv.y;
                }
                if (EPI == 2) {
                    v0 = gelu_tanh(v0); v1 = gelu_tanh(v1);
                    __nv_bfloat162 hp, lp;
                    hp.x = __float2bfloat16(v0); hp.y = __float2bfloat16(v1);
                    lp.x = __float2bfloat16(v0 - __bfloat162float(hp.x));
                    lp.y = __float2bfloat16(v1 - __bfloat162float(hp.y));
                    *(__nv_bfloat162*)(outHi + (size_t)m * Nn + n) = hp;
                    *(__nv_bfloat162*)(outLo + (size_t)m * Nn + n) = lp;
                } else {
                    *(float2*)(outF + (size_t)m * Nn + n) = make_float2(v0, v1);
                }
            }
        }
    }
}

// ---------------- kernel: xt = p2t(x1)+p2t(x2)+p2t(x3) ----------------
__global__ void k_fuse(const float* __restrict__ x1, const float* __restrict__ x2,
                       const float* __restrict__ x3) {
    __shared__ float t[32][33];
    const int b  = blockIdx.z;
    const int c0 = blockIdx.x * 32;
    const int l0 = blockIdx.y * 32;
    const int tx = threadIdx.x, ty = threadIdx.y;
    const size_t base = (size_t)b * Cc * Ll;
    for (int i = ty; i < 32; i += 8) {
        const size_t idx = base + (size_t)(c0 + i) * Ll + (l0 + tx);
        t[i][tx] = x1[idx] + x2[idx] + x3[idx];
    }
    __syncthreads();
    float* xt = BUF(OFF_XT);
    for (int i = ty; i < 32; i += 8)
        xt[((size_t)b * Ll + (l0 + i)) * Cc + (c0 + tx)] = t[tx][i];
}

// ---------------- LayerNorm(512) -> bf16 hi/lo split ----------------
__global__ void k_ln_split(const float* __restrict__ in, const float* __restrict__ w,
                           const float* __restrict__ bvec,
                           __nv_bfloat16* __restrict__ hi, __nv_bfloat16* __restrict__ lo) {
    constexpr int T = 256;
    __shared__ float red[T];
    const size_t row = blockIdx.x;
    const float* x = in + row * Cc;
    const int tid = threadIdx.x;

    const float a0 = x[tid], a1 = x[tid + 256];
    red[tid] = a0 + a1; __syncthreads();
    for (int o = T / 2; o > 0; o >>= 1) { if (tid < o) red[tid] += red[tid + o]; __syncthreads(); }
    const float mu = red[0] * (1.f / Cc);
    __syncthreads();
    const float d0 = a0 - mu, d1 = a1 - mu;
    red[tid] = d0 * d0 + d1 * d1; __syncthreads();
    for (int o = T / 2; o > 0; o >>= 1) { if (tid < o) red[tid] += red[tid + o]; __syncthreads(); }
    const float inv = rsqrtf(red[0] * (1.f / Cc) + 1e-5f);

#pragma unroll
    for (int p = 0; p < 2; p++) {
        const int i = tid + p * 256;
        const float v = ((p ? a1 : a0) - mu) * inv * w[i] + bvec[i];
        const __nv_bfloat16 h = __float2bfloat16(v);
        hi[row * Cc + i] = h;
        lo[row * Cc + i] = __float2bfloat16(v - __bfloat162float(h));
    }
}

// ---------------- weight split fp32 -> bf16 hi/lo ----------------
__global__ void k_split(const float* __restrict__ src, __nv_bfloat16* __restrict__ hi,
                        __nv_bfloat16* __restrict__ lo, int n) {
    const int i = blockIdx.x * 256 + threadIdx.x;
    if (i < n) {
        const float v = src[i];
        const __nv_bfloat16 h = __float2bfloat16(v);
        hi[i] = h;
        lo[i] = __float2bfloat16(v - __bfloat162float(h));
    }
}

// ---------------- fp32 SGEMM (for small x_proj) ----------------
template <int BM, int BN, int BK, int TM, int TN>
__global__ __launch_bounds__((BM / TM) * (BN / TN))
void k_gemm_f32(size_t offA, const float* __restrict__ Bw, size_t offC, int M, int Nn, int Kd) {
    constexpr int NT = (BM / TM) * (BN / TN);
    __shared__ float As[BK][BM];
    __shared__ float Bs[BK][BN];
    const float* A = BUF(offA);
    float* Cmat = BUF(offC);

    const int tid = threadIdx.x;
    const int bm = blockIdx.x * BM;
    const int bn = blockIdx.y * BN;
    const int tx = tid % (BN / TN);
    const int ty = tid / (BN / TN);

    float acc[TM][TN];
#pragma unroll
    for (int i = 0; i < TM; i++)
#pragma unroll
        for (int j = 0; j < TN; j++) acc[i][j] = 0.f;

    for (int k0 = 0; k0 < Kd; k0 += BK) {
        constexpr int AV = BM * BK / 4;
        for (int i = tid; i < AV; i += NT) {
            const int row = i / (BK / 4), kk = (i % (BK / 4)) * 4;
            const float4 v = *reinterpret_cast<const float4*>(&A[(size_t)(bm + row) * Kd + k0 + kk]);
            As[kk][row] = v.x; As[kk + 1][row] = v.y; As[kk + 2][row] = v.z; As[kk + 3][row] = v.w;
        }
        constexpr int BV = BN * BK / 4;
        for (int i = tid; i < BV; i += NT) {
            const int row = i / (BK / 4), kk = (i % (BK / 4)) * 4;
            float4 v = make_float4(0.f, 0.f, 0.f, 0.f);
            if (bn + row < Nn)
                v = *reinterpret_cast<const float4*>(&Bw[(size_t)(bn + row) * Kd + k0 + kk]);
            Bs[kk][row] = v.x; Bs[kk + 1][row] = v.y; Bs[kk + 2][row] = v.z; Bs[kk + 3][row] = v.w;
        }
        __syncthreads();
#pragma unroll
        for (int k = 0; k < BK; k++) {
            float a[TM], b[TN];
#pragma unroll
            for (int i = 0; i < TM; i++) a[i] = As[k][ty * TM + i];
#pragma unroll
            for (int j = 0; j < TN; j++) b[j] = Bs[k][tx * TN + j];
#pragma unroll
            for (int i = 0; i < TM; i++)
#pragma unroll
                for (int j = 0; j < TN; j++) acc[i][j] += a[i] * b[j];
        }
        __syncthreads();
    }
#pragma unroll
    for (int i = 0; i < TM; i++) {
        const int m = bm + ty * TM + i;
#pragma unroll
        for (int j = 0; j < TN; j++) {
            const int n = bn + tx * TN + j;
            if (n >= Nn) continue;
            Cmat[(size_t)m * Nn + n] = acc[i][j];
        }
    }
}

// ---------------- prep: transpose dt_w (K,D,R)->(K,R,D), conv_w (D,9)->(9,D) ----------------
__global__ void k_prep(const float* __restrict__ dt_w, const float* __restrict__ conv_w) {
    const int i = blockIdx.x * 256 + threadIdx.x;
    if (i < Kk * Rr * Dd) {
        const int k = i / (Rr * Dd);
        const int rem = i % (Rr * Dd);
        const int r = rem / Dd, d = rem % Dd;
        BUF(OFF_DTWT)[i] = dt_w[((size_t)k * Dd + d) * Rr + r];
    }
    if (i < 9 * Dd) {
        const int j = i / Dd, d = i % Dd;
        BUF(OFF_CONVWT)[i] = conv_w[(size_t)d * 9 + j];
    }
}

// ---------------- depthwise 3x3 conv + SiLU ----------------
__global__ void k_conv(const float* __restrict__ conv_b) {
    const int bl = blockIdx.x;
    const int d = blockIdx.y * 256 + threadIdx.x;
    const int b = bl / Ll, l = bl % Ll;
    const int h = l / Ww, w = l % Ww;
    const float* xz = BUF(OFF_XZ);
    const float* cw = BUF(OFF_CONVWT);
    float acc = 0.f;
#pragma unroll
    for (int kh = -1; kh <= 1; kh++) {
        const int hh = h + kh;
        if (hh < 0 || hh >= Hh) continue;
#pragma unroll
        for (int kw = -1; kw <= 1; kw++) {
            const int ww2 = w + kw;
            if (ww2 < 0 || ww2 >= Ww) continue;
            acc += xz[((size_t)(b * Ll + hh * Ww + ww2)) * 2 * Dd + d] *
                   cw[(size_t)((kh + 1) * 3 + (kw + 1)) * Dd + d];
        }
    }
    acc += conv_b[d];
    BUF(OFF_XC)[(size_t)bl * Dd + d] = acc / (1.f + __expf(-acc));
}

// ---------------- cross-scan ----------------
__global__ void k_xscan() {
    const int bl = blockIdx.x;
    const int d = blockIdx.y * 256 + threadIdx.x;
    const int b = bl / Ll, l = bl % Ll;
    const float* xc = BUF(OFF_XC);
    float* xs = BUF(OFF_XS);
    const float v0 = xc[(size_t)bl * Dd + d];
    const int l1 = (l % Hh) * Ww + (l / Hh);
    const float v1 = xc[((size_t)b * Ll + l1) * Dd + d];
    xs[(((size_t)(0 * Bb + b)) * Ll + l) * Dd + d] = v0;
    xs[(((size_t)(1 * Bb + b)) * Ll + l) * Dd + d] = v1;
    xs[(((size_t)(2 * Bb + b)) * Ll + (Ll - 1 - l)) * Dd + d] = v0;
    xs[(((size_t)(3 * Bb + b)) * Ll + (Ll - 1 - l)) * Dd + d] = v1;
}

// ---------------- dts = softplus(x_dbl[:, :R] @ dt_w^T + dt_b) ----------------
__global__ void k_dt(const float* __restrict__ dt_b) {
    constexpr int LT = 8;
    __shared__ float s[LT][Rr];
    const int blk = blockIdx.x;
    const int lt = blk % (Ll / LT);
    const int rem = blk / (Ll / LT);
    const int b = rem % Bb;
    const int k = rem / Bb;
    const int l0 = lt * LT;
    const int tid = threadIdx.x;
    {
        const int i = tid / Rr, r = tid % Rr;
        s[i][r] = BUF(OFF_XDBL)[(((size_t)k * Bb + b) * Ll + l0 + i) * XDBL + r];
    }
    __syncthreads();
    const float* wT = BUF(OFF_DTWT);
    float* dts = BUF(OFF_DTS);
    for (int dc = 0; dc < Dd / 256; dc++) {
        const int d = dc * 256 + tid;
        const float bias = dt_b[k * Dd + d];
        float acc[LT];
#pragma unroll
        for (int i = 0; i < LT; i++) acc[i] = bias;
        for (int r = 0; r < Rr; r++) {
            const float wv = wT[((size_t)k * Rr + r) * Dd + d];
#pragma unroll
            for (int i = 0; i < LT; i++) acc[i] += s[i][r] * wv;
        }
#pragma unroll
        for (int i = 0; i < LT; i++) {
            const float x = acc[i];
            const float sp = (x > 20.f) ? x : log1pf(__expf(x));
            dts[(((size_t)k * Bb + b) * Ll + l0 + i) * Dd + d] = sp;
        }
    }
}

// ---------------- selective scan ----------------
__global__ void k_scan(const float* __restrict__ A_logs, const float* __restrict__ Ds) {
    const int blk = blockIdx.x;
    const int dc = blk & 3;
    const int kb = blk >> 2;
    const int b = kb % Bb;
    const int k = kb / Bb;
    const int d = dc * 256 + threadIdx.x;

    float Aa[Nst];
#pragma unroll
    for (int n = 0; n < Nst; n++) Aa[n] = -__expf(A_logs[((size_t)k * Dd + d) * Nst + n]);
    const float Dv = Ds[k * Dd + d];

    const float* xs = BUF(OFF_XS);
    const float* dts = BUF(OFF_DTS);
    const float* xdbl = BUF(OFF_XDBL);
    float* ys = BUF(OFF_YS);

    const size_t ubase = ((size_t)k * Bb + b) * Ll * Dd + d;
    const size_t bcbase = ((size_t)k * Bb + b) * Ll * XDBL;

    float hst[Nst] = {0.f, 0.f, 0.f, 0.f};
    for (int l = 0; l < Ll; l++) {
        const float u = xs[ubase + (size_t)l * Dd];
        const float dt = dts[ubase + (size_t)l * Dd];
        const float* bc = xdbl + bcbase + (size_t)l * XDBL + Rr;
        const float du = dt * u;
        float y = 0.f;
#pragma unroll
        for (int n = 0; n < Nst; n++) {
            const float dA = __expf(dt * Aa[n]);
            hst[n] = hst[n] * dA + du * bc[n];
            y += hst[n] * bc[Nst + n];
        }
        ys[ubase + (size_t)l * Dd] = y + Dv * u;
    }
}

// ---------------- cross-merge + out_norm LN + SiLU(z) gate -> bf16 hi/lo ----------------
__global__ void k_merge(const float* __restrict__ onw, const float* __restrict__ onb,
                        __nv_bfloat16* __restrict__ ygHi, __nv_bfloat16* __restrict__ ygLo) {
    constexpr int T = 256;
    __shared__ float bufr[Dd];
    __shared__ float red[T];
    const int bl = blockIdx.x;
    const int b = bl / Ll, l = bl % Ll;
    const int h = l / Ww, w = l % Ww;
    const int lt = w * Hh + h;
    const int tid = threadIdx.x;
    const float* ys = BUF(OFF_YS);

    const size_t r0 = (((size_t)(0 * Bb + b)) * Ll + l) * Dd;
    const size_t r1 = (((size_t)(1 * Bb + b)) * Ll + lt) * Dd;
    const size_t r2 = (((size_t)(2 * Bb + b)) * Ll + (Ll - 1 - l)) * Dd;
    const size_t r3 = (((size_t)(3 * Bb + b)) * Ll + (Ll - 1 - lt)) * Dd;

    float s = 0.f;
#pragma unroll
    for (int it = 0; it < Dd / T; it++) {
        const int d = tid + it * T;
        const float v = ys[r0 + d] + ys[r1 + d] + ys[r2 + d] + ys[r3 + d];
        bufr[d] = v; s += v;
    }
    red[tid] = s; __syncthreads();
    for (int o = T / 2; o > 0; o >>= 1) { if (tid < o) red[tid] += red[tid + o]; __syncthreads(); }
    const float mu = red[0] * (1.f / Dd);
    __syncthreads();
    float s2 = 0.f;
#pragma unroll
    for (int it = 0; it < Dd / T; it++) {
        const int d = tid + it * T;
        const float dv = bufr[d] - mu; s2 += dv * dv;
    }
    red[tid] = s2; __syncthreads();
    for (int o = T / 2; o > 0; o >>= 1) { if (tid < o) red[tid] += red[tid + o]; __syncthreads(); }
    const float inv = rsqrtf(red[0] * (1.f / Dd) + 1e-5f);

    const float* xz = BUF(OFF_XZ);
#pragma unroll
    for (int it = 0; it < Dd / T; it++) {
        const int d = tid + it * T;
        const float zv = xz[(size_t)bl * 2 * Dd + Dd + d];
        const float g = zv / (1.f + __expf(-zv));
        const float v = ((bufr[d] - mu) * inv * onw[d] + onb[d]) * g;
        const __nv_bfloat16 hh = __float2bfloat16(v);
        ygHi[(size_t)bl * Dd + d] = hh;
        ygLo[(size_t)bl * Dd + d] = __float2bfloat16(v - __bfloat162float(hh));
    }
}

// ---------------- final token2patch transpose ----------------
__global__ void k_out(float* __restrict__ out) {
    __shared__ float t[32][33];
    const int b = blockIdx.z;
    const int l0 = blockIdx.x * 32;
    const int c0 = blockIdx.y * 32;
    const int tx = threadIdx.x, ty = threadIdx.y;
    const float* xf = BUF(OFF_XFIN);
    for (int i = ty; i < 32; i += 8)
        t[i][tx] = xf[((size_t)b * Ll + (l0 + i)) * Cc + (c0 + tx)];
    __syncthreads();
    for (int i = ty; i < 32; i += 8)
        out[((size_t)b * Cc + (c0 + i)) * Ll + (l0 + tx)] = t[tx][i];
}

// ---------------- launch ----------------
extern "C" void kernel_launch(void* const* d_in, const int* in_sizes, int n_in,
                              void* d_out, int out_size) {
    const float* x1        = (const float*)d_in[0];
    const float* x2        = (const float*)d_in[1];
    const float* x3        = (const float*)d_in[2];
    const float* ln1_w     = (const float*)d_in[3];
    const float* ln1_b     = (const float*)d_in[4];
    const float* in_proj_w = (const float*)d_in[5];
    const float* in_proj_b = (const float*)d_in[6];
    const float* conv_w    = (const float*)d_in[7];
    const float* conv_b    = (const float*)d_in[8];
    const float* x_proj_w  = (const float*)d_in[9];
    const float* dt_w      = (const float*)d_in[10];
    const float* dt_b      = (const float*)d_in[11];
    const float* A_logs    = (const float*)d_in[12];
    const float* Ds        = (const float*)d_in[13];
    const float* out_norm_w= (const float*)d_in[14];
    const float* out_norm_b= (const float*)d_in[15];
    const float* out_proj_w= (const float*)d_in[16];
    const float* out_proj_b= (const float*)d_in[17];
    const float* ln2_w     = (const float*)d_in[18];
    const float* ln2_b     = (const float*)d_in[19];
    const float* fc1_w     = (const float*)d_in[20];
    const float* fc1_b     = (const float*)d_in[21];
    const float* fc2_w     = (const float*)d_in[22];
    const float* fc2_b     = (const float*)d_in[23];
    float* out = (float*)d_out;

    void* pf = nullptr;  cudaGetSymbolAddress(&pf, g_buf);
    void* pbh = nullptr; cudaGetSymbolAddress(&pbh, g_bh);
    float* F = (float*)pf;
    __nv_bfloat16* BH = (__nv_bfloat16*)pbh;

    // 1. fuse + transpose -> xt
    k_fuse<<<dim3(Cc / 32, Ll / 32, Bb), dim3(32, 8)>>>(x1, x2, x3);
    // 2. weight splits
    k_split<<<(2 * Dd * Cc + 255) / 256, 256>>>(in_proj_w, BH + BH_WIP_HI, BH + BH_WIP_LO, 2 * Dd * Cc);
    k_split<<<(Cc * Dd + 255) / 256, 256>>>(out_proj_w, BH + BH_WOP_HI, BH + BH_WOP_LO, Cc * Dd);
    k_split<<<(MH * Cc + 255) / 256, 256>>>(fc1_w, BH + BH_WF1_HI, BH + BH_WF1_LO, MH * Cc);
    k_split<<<(Cc * MH + 255) / 256, 256>>>(fc2_w, BH + BH_WF2_HI, BH + BH_WF2_LO, Cc * MH);
    // 3. LN1 -> bf16 split
    k_ln_split<<<BL, 256>>>(F + OFF_XT, ln1_w, ln1_b, BH + BH_H_HI, BH + BH_H_LO);
    // 4. in_proj (tensor cores): xz fp32
    k_gemm_mma<0><<<dim3(BL / 128, 2 * Dd / 128), 256>>>(
        BH + BH_H_HI, BH + BH_H_LO, BH + BH_WIP_HI, BH + BH_WIP_LO,
        in_proj_b, nullptr, F + OFF_XZ, nullptr, nullptr, 2 * Dd, Cc);
    // 5. weight transposes for dt/conv
    k_prep<<<(Kk * Rr * Dd + 255) / 256, 256>>>(dt_w, conv_w);
    // 6. conv + silu
    k_conv<<<dim3(BL, Dd / 256), 256>>>(conv_b);
    // 7. cross-scan
    k_xscan<<<dim3(BL, Dd / 256), 256>>>();
    // 8. x_proj (fp32, small N)
    for (int k = 0; k < Kk; k++) {
        k_gemm_f32<128, 64, 16, 8, 4><<<dim3(BL / 128, 1), 256>>>(
            OFF_XS + (size_t)k * BL * Dd, x_proj_w + (size_t)k * XDBL * Dd,
            OFF_XDBL + (size_t)k * BL * XDBL, BL, XDBL, Dd);
    }
    // 9. dt projection + softplus
    k_dt<<<Kk * Bb * (Ll / 8), 256>>>(dt_b);
    // 10. selective scan
    k_scan<<<Kk * Bb * 4, 256>>>(A_logs, Ds);
    // 11. merge + LN + gate -> bf16 split
    k_merge<<<BL, 256>>>(out_norm_w, out_norm_b, BH + BH_YG_HI, BH + BH_YG_LO);
    // 12. out_proj + residual(xt) -> xres fp32
    k_gemm_mma<1><<<dim3(BL / 128, Cc / 128), 256>>>(
        BH + BH_YG_HI, BH + BH_YG_LO, BH + BH_WOP_HI, BH + BH_WOP_LO,
        out_proj_b, F + OFF_XT, F + OFF_XRES, nullptr, nullptr, Cc, Dd);
    // 13. LN2 -> bf16 split
    k_ln_split<<<BL, 256>>>(F + OFF_XRES, ln2_w, ln2_b, BH + BH_M1_HI, BH + BH_M1_LO);
    // 14. fc1 + gelu -> bf16 split
    k_gemm_mma<2><<<dim3(BL / 128, MH / 128), 256>>>(
        BH + BH_M1_HI, BH + BH_M1_LO, BH + BH_WF1_HI, BH + BH_WF1_LO,
        fc1_b, nullptr, nullptr, BH + BH_MH_HI, BH + BH_MH_LO, MH, Cc);
    // 15. fc2 + residual(xres) -> xfin fp32
    k_gemm_mma<1><<<dim3(BL / 128, Cc / 128), 256>>>(
        BH + BH_MH_HI, BH + BH_MH_LO, BH + BH_WF2_HI, BH + BH_WF2_LO,
        fc2_b, F + OFF_XRES, F + OFF_XFIN, nullptr, nullptr, Cc, MH);
    // 16. token2patch
    k_out<<<dim3(Ll / 32, Cc / 32, Bb), dim3(32, 8)>>>(out);
}

// round 4
// speedup vs baseline: 2.6582x; 1.5560x over previous
#include <cuda_runtime.h>
#include <cuda_fp16.h>
#include <math.h>
#include <stdint.h>

// ---------------- problem dims ----------------
constexpr int Bb = 32, Cc = 512, Hh = 24, Ww = 24;
constexpr int Ll = Hh * Ww;          // 576
constexpr int Dd = 1024, Kk = 4, Nst = 4, Rr = 32, MH = 2048;
constexpr int BL = Bb * Ll;          // 18432
constexpr int XDW = 160;             // 4 * (R + 2N)

// ---------------- fp32 scratch ----------------
constexpr size_t OFF_XT     = 0;
constexpr size_t OFF_XZ     = OFF_XT     + (size_t)BL * Cc;
constexpr size_t OFF_XC     = OFF_XZ     + (size_t)BL * 2 * Dd;
constexpr size_t OFF_XDBL   = OFF_XC     + (size_t)BL * Dd;          // xd_all [BL,160]
constexpr size_t OFF_DTS    = OFF_XDBL   + (size_t)BL * XDW;
constexpr size_t OFF_YS     = OFF_DTS    + (size_t)Kk * BL * Dd;
constexpr size_t OFF_XRES   = OFF_YS     + (size_t)Kk * BL * Dd;
constexpr size_t OFF_XFIN   = OFF_XRES   + (size_t)BL * Cc;
constexpr size_t OFF_DTWT   = OFF_XFIN   + (size_t)BL * Cc;
constexpr size_t OFF_CONVWT = OFF_DTWT   + (size_t)Kk * Rr * Dd;
constexpr size_t TOTF       = OFF_CONVWT + (size_t)9 * Dd;

__device__ __align__(128) float g_buf[TOTF];
#define BUF(off) (g_buf + (off))

// ---------------- fp16 scratch ----------------
constexpr size_t HH_H      = 0;
constexpr size_t HH_YG     = HH_H      + (size_t)BL * Cc;
constexpr size_t HH_M1     = HH_YG     + (size_t)BL * Dd;
constexpr size_t HH_MH     = HH_M1     + (size_t)BL * Cc;
constexpr size_t HH_WIP_HI = HH_MH     + (size_t)BL * MH;
constexpr size_t HH_WIP_LO = HH_WIP_HI + (size_t)2 * Dd * Cc;
constexpr size_t HH_WOP_HI = HH_WIP_LO + (size_t)2 * Dd * Cc;
constexpr size_t HH_WOP_LO = HH_WOP_HI + (size_t)Cc * Dd;
constexpr size_t HH_WF1_HI = HH_WOP_LO + (size_t)Cc * Dd;
constexpr size_t HH_WF1_LO = HH_WF1_HI + (size_t)MH * Cc;
constexpr size_t HH_WF2_HI = HH_WF1_LO + (size_t)MH * Cc;
constexpr size_t HH_WF2_LO = HH_WF2_HI + (size_t)Cc * MH;
constexpr size_t TOTH      = HH_WF2_LO + (size_t)Cc * MH;

__device__ __align__(128) __half g_hh[TOTH];

// ---------------- helpers ----------------
__device__ __forceinline__ uint32_t s2u(const void* p) {
    uint32_t a;
    asm("{ .reg .u64 t; cvta.to.shared.u64 t, %1; cvt.u32.u64 %0, t; }" : "=r"(a) : "l"(p));
    return a;
}
__device__ __forceinline__ void cpasync16(uint32_t dst, const void* src) {
    asm volatile("cp.async.cg.shared.global [%0], [%1], 16;" :: "r"(dst), "l"(src));
}
__device__ __forceinline__ void cpcommit() { asm volatile("cp.async.commit_group;" ::: "memory"); }
__device__ __forceinline__ void cpwait2() { asm volatile("cp.async.wait_group 2;" ::: "memory"); }
__device__ __forceinline__ void ldm_x4(uint32_t* d, uint32_t addr) {
    asm volatile("ldmatrix.sync.aligned.m8n8.x4.shared.b16 {%0,%1,%2,%3}, [%4];"
                 : "=r"(d[0]), "=r"(d[1]), "=r"(d[2]), "=r"(d[3]) : "r"(addr));
}
__device__ __forceinline__ void ldm_x2(uint32_t* d, uint32_t addr) {
    asm volatile("ldmatrix.sync.aligned.m8n8.x2.shared.b16 {%0,%1}, [%2];"
                 : "=r"(d[0]), "=r"(d[1]) : "r"(addr));
}
__device__ __forceinline__ void mma_f16(float* c, const uint32_t* a, const uint32_t* b) {
    asm volatile(
        "mma.sync.aligned.m16n8k16.row.col.f32.f16.f16.f32 "
        "{%0,%1,%2,%3}, {%4,%5,%6,%7}, {%8,%9}, {%0,%1,%2,%3};"
        : "+f"(c[0]), "+f"(c[1]), "+f"(c[2]), "+f"(c[3])
        : "r"(a[0]), "r"(a[1]), "r"(a[2]), "r"(a[3]), "r"(b[0]), "r"(b[1]));
}
__device__ __forceinline__ float gelu_tanh(float x) {
    return 0.5f * x * (1.f + tanhf(0.7978845608028654f * (x + 0.044715f * x * x * x)));
}
// direction-k read permutation over L
__device__ __forceinline__ int permL(int k, int l) {
    int ll = (k & 2) ? (Ll - 1 - l) : l;
    if (k & 1) ll = (ll % Hh) * Ww + (ll / Hh);
    return ll;
}

// ---------------- fp16 2-pass tensor-core GEMM: C[M,N] = A @ (B_hi+B_lo)^T ----------------
// A single fp16 activations; B split hi/lo fp16 weights. fp32 accumulation.
// EPI 0: +bias -> fp32. EPI 1: +bias +res -> fp32. EPI 2: gelu(+bias) -> fp16.
constexpr int GEMM_SMEM = 4 * 16384;   // 4 stages x (A 8KB + B 8KB)

template <int EPI>
__global__ __launch_bounds__(256)
void k_gemm_mma(const __half* __restrict__ A,
                const __half* __restrict__ Bhi, const __half* __restrict__ Blo,
                const float* __restrict__ bias, const float* __restrict__ res,
                float* __restrict__ outF, __half* __restrict__ outH,
                int Nn, int Kd) {
    extern __shared__ __align__(128) char sm[];
    const int tid = threadIdx.x, lane = tid & 31, wid = tid >> 5;
    const int wm = wid & 1, wn = wid >> 1;
    const int bm = blockIdx.x * 128, bn = blockIdx.y * 128;
    const int nk = Kd >> 5, T = 2 * nk;
    const __half* pb[2] = {Bhi, Blo};

    const int rr = tid >> 2, cc = tid & 3;
    const uint32_t swLo = rr * 64 + (((cc + (rr >> 1)) & 3) << 4);
    const uint32_t swHi = (rr + 64) * 64 + (((cc + (rr >> 1)) & 3) << 4);
    const uint32_t smBase = s2u(sm);

    auto issue = [&](int it) {
        const int p = it >= nk;
        const int kc = (it - p * nk) * 32;
        const uint32_t st = smBase + (uint32_t)(it & 3) * 16384;
        const __half* Bp = pb[p];
        cpasync16(st + swLo,        A  + (size_t)(bm + rr)      * Kd + kc + cc * 8);
        cpasync16(st + swHi,        A  + (size_t)(bm + rr + 64) * Kd + kc + cc * 8);
        cpasync16(st + 8192 + swLo, Bp + (size_t)(bn + rr)      * Kd + kc + cc * 8);
        cpasync16(st + 8192 + swHi, Bp + (size_t)(bn + rr + 64) * Kd + kc + cc * 8);
    };

    float acc[4][4][4];
#pragma unroll
    for (int i = 0; i < 4; i++)
#pragma unroll
        for (int j = 0; j < 4; j++)
#pragma unroll
            for (int q = 0; q < 4; q++) acc[i][j][q] = 0.f;

    issue(0); cpcommit();
    issue(1); cpcommit();
    issue(2); cpcommit();

    for (int it = 0; it < T; it++) {
        cpwait2();
        __syncthreads();
        if (it + 3 < T) issue(it + 3);
        cpcommit();                         // unconditional: keeps wait_group<2> exact at tail
        const uint32_t aB = smBase + (uint32_t)(it & 3) * 16384;
        const uint32_t bB = aB + 8192;
#pragma unroll
        for (int s16 = 0; s16 < 2; s16++) {
            uint32_t af[4][4], bfr[4][2];
#pragma unroll
            for (int mi = 0; mi < 4; mi++) {
                const int r = wm * 64 + mi * 16 + (lane & 15);
                const int c = 2 * s16 + (lane >> 4);
                ldm_x4(af[mi], aB + r * 64 + (((c + (r >> 1)) & 3) << 4));
            }
#pragma unroll
            for (int ni = 0; ni < 4; ni++) {
                const int i = lane & 15;
                const int r = wn * 32 + ni * 8 + (i & 7);
                const int c = 2 * s16 + (i >> 3);
                ldm_x2(bfr[ni], bB + r * 64 + (((c + (r >> 1)) & 3) << 4));
            }
#pragma unroll
            for (int mi = 0; mi < 4; mi++)
#pragma unroll
                for (int ni = 0; ni < 4; ni++)
                    mma_f16(acc[mi][ni], af[mi], bfr[ni]);
        }
    }

    // epilogue
#pragma unroll
    for (int mi = 0; mi < 4; mi++) {
#pragma unroll
        for (int ni = 0; ni < 4; ni++) {
            const int n = bn + wn * 32 + ni * 8 + (lane & 3) * 2;
            const float b0v = __ldg(bias + n), b1v = __ldg(bias + n + 1);
#pragma unroll
            for (int h = 0; h < 2; h++) {
                const int m = bm + wm * 64 + mi * 16 + (lane >> 2) + h * 8;
                float v0 = acc[mi][ni][h * 2 + 0] + b0v;
                float v1 = acc[mi][ni][h * 2 + 1] + b1v;
                if (EPI == 1) {
                    const float2 rv = *(const float2*)(res + (size_t)m * Nn + n);
                    v0 += rv.x; v1 += rv.y;
                }
                if (EPI == 2) {
                    v0 = gelu_tanh(v0); v1 = gelu_tanh(v1);
                    __half2 hp; hp.x = __float2half(v0); hp.y = __float2half(v1);
                    *(__half2*)(outH + (size_t)m * Nn + n) = hp;
                } else {
                    *(float2*)(outF + (size_t)m * Nn + n) = make_float2(v0, v1);
                }
            }
        }
    }
}

// ---------------- xt = p2t(x1)+p2t(x2)+p2t(x3) ----------------
__global__ void k_fuse(const float* __restrict__ x1, const float* __restrict__ x2,
                       const float* __restrict__ x3) {
    __shared__ float t[32][33];
    const int b  = blockIdx.z;
    const int c0 = blockIdx.x * 32;
    const int l0 = blockIdx.y * 32;
    const int tx = threadIdx.x, ty = threadIdx.y;
    const size_t base = (size_t)b * Cc * Ll;
    for (int i = ty; i < 32; i += 8) {
        const size_t idx = base + (size_t)(c0 + i) * Ll + (l0 + tx);
        t[i][tx] = x1[idx] + x2[idx] + x3[idx];
    }
    __syncthreads();
    float* xt = BUF(OFF_XT);
    for (int i = ty; i < 32; i += 8)
        xt[((size_t)b * Ll + (l0 + i)) * Cc + (c0 + tx)] = t[tx][i];
}

// ---------------- LayerNorm(512) -> fp16 ----------------
__global__ void k_ln_h(const float* __restrict__ in, const float* __restrict__ w,
                       const float* __restrict__ bvec, __half* __restrict__ ho) {
    constexpr int T = 256;
    __shared__ float red[T];
    const size_t row = blockIdx.x;
    const float* x = in + row * Cc;
    const int tid = threadIdx.x;

    const float a0 = x[tid], a1 = x[tid + 256];
    red[tid] = a0 + a1; __syncthreads();
    for (int o = T / 2; o > 0; o >>= 1) { if (tid < o) red[tid] += red[tid + o]; __syncthreads(); }
    const float mu = red[0] * (1.f / Cc);
    __syncthreads();
    const float d0 = a0 - mu, d1 = a1 - mu;
    red[tid] = d0 * d0 + d1 * d1; __syncthreads();
    for (int o = T / 2; o > 0; o >>= 1) { if (tid < o) red[tid] += red[tid + o]; __syncthreads(); }
    const float inv = rsqrtf(red[0] * (1.f / Cc) + 1e-5f);

    ho[row * Cc + tid]       = __float2half((a0 - mu) * inv * w[tid] + bvec[tid]);
    ho[row * Cc + tid + 256] = __float2half((a1 - mu) * inv * w[tid + 256] + bvec[tid + 256]);
}

// ---------------- weight split fp32 -> fp16 hi/lo ----------------
__global__ void k_split_w(const float* __restrict__ src, __half* __restrict__ hi,
                          __half* __restrict__ lo, int n) {
    const int i = blockIdx.x * 256 + threadIdx.x;
    if (i < n) {
        const float v = src[i];
        const __half h = __float2half(v);
        hi[i] = h;
        lo[i] = __float2half(v - __half2float(h));
    }
}

// ---------------- fp32 SGEMM (x_proj: xd_all = xc @ Wall^T, N=160) ----------------
template <int BM, int BN, int BK, int TM, int TN>
__global__ __launch_bounds__((BM / TM) * (BN / TN))
void k_gemm_f32(size_t offA, const float* __restrict__ Bw, size_t offC, int M, int Nn, int Kd) {
    constexpr int NT = (BM / TM) * (BN / TN);
    __shared__ float As[BK][BM];
    __shared__ float Bs[BK][BN];
    const float* A = BUF(offA);
    float* Cmat = BUF(offC);

    const int tid = threadIdx.x;
    const int bm = blockIdx.x * BM;
    const int bn = blockIdx.y * BN;
    const int tx = tid % (BN / TN);
    const int ty = tid / (BN / TN);

    float acc[TM][TN];
#pragma unroll
    for (int i = 0; i < TM; i++)
#pragma unroll
        for (int j = 0; j < TN; j++) acc[i][j] = 0.f;

    for (int k0 = 0; k0 < Kd; k0 += BK) {
        constexpr int AV = BM * BK / 4;
        for (int i = tid; i < AV; i += NT) {
            const int row = i / (BK / 4), kk = (i % (BK / 4)) * 4;
            const float4 v = *reinterpret_cast<const float4*>(&A[(size_t)(bm + row) * Kd + k0 + kk]);
            As[kk][row] = v.x; As[kk + 1][row] = v.y; As[kk + 2][row] = v.z; As[kk + 3][row] = v.w;
        }
        constexpr int BV = BN * BK / 4;
        for (int i = tid; i < BV; i += NT) {
            const int row = i / (BK / 4), kk = (i % (BK / 4)) * 4;
            float4 v = make_float4(0.f, 0.f, 0.f, 0.f);
            if (bn + row < Nn)
                v = *reinterpret_cast<const float4*>(&Bw[(size_t)(bn + row) * Kd + k0 + kk]);
            Bs[kk][row] = v.x; Bs[kk + 1][row] = v.y; Bs[kk + 2][row] = v.z; Bs[kk + 3][row] = v.w;
        }
        __syncthreads();
#pragma unroll
        for (int k = 0; k < BK; k++) {
            float a[TM], b[TN];
#pragma unroll
            for (int i = 0; i < TM; i++) a[i] = As[k][ty * TM + i];
#pragma unroll
            for (int j = 0; j < TN; j++) b[j] = Bs[k][tx * TN + j];
#pragma unroll
            for (int i = 0; i < TM; i++)
#pragma unroll
                for (int j = 0; j < TN; j++) acc[i][j] += a[i] * b[j];
        }
        __syncthreads();
    }
#pragma unroll
    for (int i = 0; i < TM; i++) {
        const int m = bm + ty * TM + i;
#pragma unroll
        for (int j = 0; j < TN; j++) {
            const int n = bn + tx * TN + j;
            if (n >= Nn) continue;
            Cmat[(size_t)m * Nn + n] = acc[i][j];
        }
    }
}

// ---------------- prep: dt_w (K,D,R)->(K,R,D), conv_w (D,9)->(9,D) ----------------
__global__ void k_prep(const float* __restrict__ dt_w, const float* __restrict__ conv_w) {
    const int i = blockIdx.x * 256 + threadIdx.x;
    if (i < Kk * Rr * Dd) {
        const int k = i / (Rr * Dd);
        const int rem = i % (Rr * Dd);
        const int r = rem / Dd, d = rem % Dd;
        BUF(OFF_DTWT)[i] = dt_w[((size_t)k * Dd + d) * Rr + r];
    }
    if (i < 9 * Dd) {
        const int j = i / Dd, d = i % Dd;
        BUF(OFF_CONVWT)[i] = conv_w[(size_t)d * 9 + j];
    }
}

// ---------------- depthwise 3x3 conv + SiLU ----------------
__global__ void k_conv(const float* __restrict__ conv_b) {
    const int bl = blockIdx.x;
    const int d = blockIdx.y * 256 + threadIdx.x;
    const int b = bl / Ll, l = bl % Ll;
    const int h = l / Ww, w = l % Ww;
    const float* xz = BUF(OFF_XZ);
    const float* cw = BUF(OFF_CONVWT);
    float acc = 0.f;
#pragma unroll
    for (int kh = -1; kh <= 1; kh++) {
        const int hh = h + kh;
        if (hh < 0 || hh >= Hh) continue;
#pragma unroll
        for (int kw = -1; kw <= 1; kw++) {
            const int ww2 = w + kw;
            if (ww2 < 0 || ww2 >= Ww) continue;
            acc += xz[((size_t)(b * Ll + hh * Ww + ww2)) * 2 * Dd + d] *
                   cw[(size_t)((kh + 1) * 3 + (kw + 1)) * Dd + d];
        }
    }
    acc += conv_b[d];
    BUF(OFF_XC)[(size_t)bl * Dd + d] = acc / (1.f + __expf(-acc));
}

// ---------------- dts = softplus(xd_r @ dt_w^T + dt_b), sourced via permL ----------------
__global__ void k_dt(const float* __restrict__ dt_b) {
    constexpr int LT = 8;
    __shared__ float s[LT][Rr];
    const int blk = blockIdx.x;
    const int lt = blk % (Ll / LT);
    const int rem = blk / (Ll / LT);
    const int b = rem % Bb;
    const int k = rem / Bb;
    const int l0 = lt * LT;
    const int tid = threadIdx.x;
    {
        const int i = tid / Rr, r = tid % Rr;
        const int pl = permL(k, l0 + i);
        s[i][r] = BUF(OFF_XDBL)[((size_t)b * Ll + pl) * XDW + k * 40 + r];
    }
    __syncthreads();
    const float* wT = BUF(OFF_DTWT);
    float* dts = BUF(OFF_DTS);
    for (int dc = 0; dc < Dd / 256; dc++) {
        const int d = dc * 256 + tid;
        const float bias = dt_b[k * Dd + d];
        float acc[LT];
#pragma unroll
        for (int i = 0; i < LT; i++) acc[i] = bias;
        for (int r = 0; r < Rr; r++) {
            const float wv = wT[((size_t)k * Rr + r) * Dd + d];
#pragma unroll
            for (int i = 0; i < LT; i++) acc[i] += s[i][r] * wv;
        }
#pragma unroll
        for (int i = 0; i < LT; i++) {
            const float x = acc[i];
            const float sp = (x > 20.f) ? x : log1pf(__expf(x));
            dts[(((size_t)k * Bb + b) * Ll + l0 + i) * Dd + d] = sp;
        }
    }
}

// ---------------- selective scan (u, B, C read via permL; no xs tensor) ----------------
__global__ void k_scan(const float* __restrict__ A_logs, const float* __restrict__ Ds) {
    const int blk = blockIdx.x;
    const int dc = blk & 3;
    const int kb = blk >> 2;
    const int b = kb % Bb;
    const int k = kb / Bb;
    const int d = dc * 256 + threadIdx.x;

    float Aa[Nst];
#pragma unroll
    for (int n = 0; n < Nst; n++) Aa[n] = -__expf(A_logs[((size_t)k * Dd + d) * Nst + n]);
    const float Dv = Ds[k * Dd + d];

    const float* xc = BUF(OFF_XC) + (size_t)b * Ll * Dd + d;
    const float* dts = BUF(OFF_DTS) + ((size_t)k * Bb + b) * Ll * Dd + d;
    const float* xd = BUF(OFF_XDBL) + (size_t)b * Ll * XDW + k * 40 + Rr;
    float* ys = BUF(OFF_YS) + ((size_t)k * Bb + b) * Ll * Dd + d;

    float hst[Nst] = {0.f, 0.f, 0.f, 0.f};
    for (int l = 0; l < Ll; l++) {
        const int pl = permL(k, l);
        const float u = xc[(size_t)pl * Dd];
        const float dt = dts[(size_t)l * Dd];
        const float* bc = xd + (size_t)pl * XDW;
        const float du = dt * u;
        float y = 0.f;
#pragma unroll
        for (int n = 0; n < Nst; n++) {
            const float dA = __expf(dt * Aa[n]);
            hst[n] = hst[n] * dA + du * bc[n];
            y += hst[n] * bc[Nst + n];
        }
        ys[(size_t)l * Dd] = y + Dv * u;
    }
}

// ---------------- cross-merge + out_norm LN + SiLU(z) gate -> fp16 ----------------
__global__ void k_merge(const float* __restrict__ onw, const float* __restrict__ onb,
                        __half* __restrict__ yg) {
    constexpr int T = 256;
    __shared__ float bufr[Dd];
    __shared__ float red[T];
    const int bl = blockIdx.x;
    const int b = bl / Ll, l = bl % Ll;
    const int h = l / Ww, w = l % Ww;
    const int lt = w * Hh + h;
    const int tid = threadIdx.x;
    const float* ys = BUF(OFF_YS);

    const size_t r0 = (((size_t)(0 * Bb + b)) * Ll + l) * Dd;
    const size_t r1 = (((size_t)(1 * Bb + b)) * Ll + lt) * Dd;
    const size_t r2 = (((size_t)(2 * Bb + b)) * Ll + (Ll - 1 - l)) * Dd;
    const size_t r3 = (((size_t)(3 * Bb + b)) * Ll + (Ll - 1 - lt)) * Dd;

    float s = 0.f;
#pragma unroll
    for (int it = 0; it < Dd / T; it++) {
        const int d = tid + it * T;
        const float v = ys[r0 + d] + ys[r1 + d] + ys[r2 + d] + ys[r3 + d];
        bufr[d] = v; s += v;
    }
    red[tid] = s; __syncthreads();
    for (int o = T / 2; o > 0; o >>= 1) { if (tid < o) red[tid] += red[tid + o]; __syncthreads(); }
    const float mu = red[0] * (1.f / Dd);
    __syncthreads();
    float s2 = 0.f;
#pragma unroll
    for (int it = 0; it < Dd / T; it++) {
        const int d = tid + it * T;
        const float dv = bufr[d] - mu; s2 += dv * dv;
    }
    red[tid] = s2; __syncthreads();
    for (int o = T / 2; o > 0; o >>= 1) { if (tid < o) red[tid] += red[tid + o]; __syncthreads(); }
    const float inv = rsqrtf(red[0] * (1.f / Dd) + 1e-5f);

    const float* xz = BUF(OFF_XZ);
#pragma unroll
    for (int it = 0; it < Dd / T; it++) {
        const int d = tid + it * T;
        const float zv = xz[(size_t)bl * 2 * Dd + Dd + d];
        const float g = zv / (1.f + __expf(-zv));
        yg[(size_t)bl * Dd + d] = __float2half(((bufr[d] - mu) * inv * onw[d] + onb[d]) * g);
    }
}

// ---------------- final token2patch transpose ----------------
__global__ void k_out(float* __restrict__ out) {
    __shared__ float t[32][33];
    const int b = blockIdx.z;
    const int l0 = blockIdx.x * 32;
    const int c0 = blockIdx.y * 32;
    const int tx = threadIdx.x, ty = threadIdx.y;
    const float* xf = BUF(OFF_XFIN);
    for (int i = ty; i < 32; i += 8)
        t[i][tx] = xf[((size_t)b * Ll + (l0 + i)) * Cc + (c0 + tx)];
    __syncthreads();
    for (int i = ty; i < 32; i += 8)
        out[((size_t)b * Cc + (c0 + i)) * Ll + (l0 + tx)] = t[tx][i];
}

// ---------------- launch ----------------
extern "C" void kernel_launch(void* const* d_in, const int* in_sizes, int n_in,
                              void* d_out, int out_size) {
    const float* x1        = (const float*)d_in[0];
    const float* x2        = (const float*)d_in[1];
    const float* x3        = (const float*)d_in[2];
    const float* ln1_w     = (const float*)d_in[3];
    const float* ln1_b     = (const float*)d_in[4];
    const float* in_proj_w = (const float*)d_in[5];
    const float* in_proj_b = (const float*)d_in[6];
    const float* conv_w    = (const float*)d_in[7];
    const float* conv_b    = (const float*)d_in[8];
    const float* x_proj_w  = (const float*)d_in[9];
    const float* dt_w      = (const float*)d_in[10];
    const float* dt_b      = (const float*)d_in[11];
    const float* A_logs    = (const float*)d_in[12];
    const float* Ds        = (const float*)d_in[13];
    const float* out_norm_w= (const float*)d_in[14];
    const float* out_norm_b= (const float*)d_in[15];
    const float* out_proj_w= (const float*)d_in[16];
    const float* out_proj_b= (const float*)d_in[17];
    const float* ln2_w     = (const float*)d_in[18];
    const float* ln2_b     = (const float*)d_in[19];
    const float* fc1_w     = (const float*)d_in[20];
    const float* fc1_b     = (const float*)d_in[21];
    const float* fc2_w     = (const float*)d_in[22];
    const float* fc2_b     = (const float*)d_in[23];
    float* out = (float*)d_out;

    void* pf = nullptr;  cudaGetSymbolAddress(&pf, g_buf);
    void* ph = nullptr;  cudaGetSymbolAddress(&ph, g_hh);
    float* F = (float*)pf;
    __half* HB = (__half*)ph;

    static bool attr_done = false;
    if (!attr_done) {
        cudaFuncSetAttribute(k_gemm_mma<0>, cudaFuncAttributeMaxDynamicSharedMemorySize, GEMM_SMEM);
        cudaFuncSetAttribute(k_gemm_mma<1>, cudaFuncAttributeMaxDynamicSharedMemorySize, GEMM_SMEM);
        cudaFuncSetAttribute(k_gemm_mma<2>, cudaFuncAttributeMaxDynamicSharedMemorySize, GEMM_SMEM);
        attr_done = true;
    }

    // 1. fuse + transpose -> xt
    k_fuse<<<dim3(Cc / 32, Ll / 32, Bb), dim3(32, 8)>>>(x1, x2, x3);
    // 2. weight splits (fp16 hi/lo)
    k_split_w<<<(2 * Dd * Cc + 255) / 256, 256>>>(in_proj_w, HB + HH_WIP_HI, HB + HH_WIP_LO, 2 * Dd * Cc);
    k_split_w<<<(Cc * Dd + 255) / 256, 256>>>(out_proj_w, HB + HH_WOP_HI, HB + HH_WOP_LO, Cc * Dd);
    k_split_w<<<(MH * Cc + 255) / 256, 256>>>(fc1_w, HB + HH_WF1_HI, HB + HH_WF1_LO, MH * Cc);
    k_split_w<<<(Cc * MH + 255) / 256, 256>>>(fc2_w, HB + HH_WF2_HI, HB + HH_WF2_LO, Cc * MH);
    // 3. LN1 -> fp16
    k_ln_h<<<BL, 256>>>(F + OFF_XT, ln1_w, ln1_b, HB + HH_H);
    // 4. in_proj (tensor cores) -> xz fp32
    k_gemm_mma<0><<<dim3(BL / 128, 2 * Dd / 128), 256, GEMM_SMEM>>>(
        HB + HH_H, HB + HH_WIP_HI, HB + HH_WIP_LO,
        in_proj_b, nullptr, F + OFF_XZ, nullptr, 2 * Dd, Cc);
    // 5. weight transposes for dt/conv
    k_prep<<<(Kk * Rr * Dd + 255) / 256, 256>>>(dt_w, conv_w);
    // 6. conv + silu -> xc
    k_conv<<<dim3(BL, Dd / 256), 256>>>(conv_b);
    // 7. x_proj: one fp32 GEMM xd_all[BL,160] = xc @ cat(W0..W3)^T
    k_gemm_f32<128, 64, 16, 8, 4><<<dim3(BL / 128, 3), 256>>>(
        OFF_XC, x_proj_w, OFF_XDBL, BL, XDW, Dd);
    // 8. dt projection + softplus -> dts
    k_dt<<<Kk * Bb * (Ll / 8), 256>>>(dt_b);
    // 9. selective scan -> ys
    k_scan<<<Kk * Bb * 4, 256>>>(A_logs, Ds);
    // 10. merge + LN + gate -> fp16 yg
    k_merge<<<BL, 256>>>(out_norm_w, out_norm_b, HB + HH_YG);
    // 11. out_proj + residual(xt) -> xres fp32
    k_gemm_mma<1><<<dim3(BL / 128, Cc / 128), 256, GEMM_SMEM>>>(
        HB + HH_YG, HB + HH_WOP_HI, HB + HH_WOP_LO,
        out_proj_b, F + OFF_XT, F + OFF_XRES, nullptr, Cc, Dd);
    // 12. LN2 -> fp16
    k_ln_h<<<BL, 256>>>(F + OFF_XRES, ln2_w, ln2_b, HB + HH_M1);
    // 13. fc1 + gelu -> fp16 mh
    k_gemm_mma<2><<<dim3(BL / 128, MH / 128), 256, GEMM_SMEM>>>(
        HB + HH_M1, HB + HH_WF1_HI, HB + HH_WF1_LO,
        fc1_b, nullptr, nullptr, HB + HH_MH, MH, Cc);
    // 14. fc2 + residual(xres) -> xfin fp32
    k_gemm_mma<1><<<dim3(BL / 128, Cc / 128), 256, GEMM_SMEM>>>(
        HB + HH_MH, HB + HH_WF2_HI, HB + HH_WF2_LO,
        fc2_b, F + OFF_XRES, F + OFF_XFIN, nullptr, Cc, MH);
    // 15. token2patch
    k_out<<<dim3(Ll / 32, Cc / 32, Bb), dim3(32, 8)>>>(out);
}

// round 5
// speedup vs baseline: 3.8037x; 1.4309x over previous
#include <cuda_runtime.h>
#include <cuda_fp16.h>
#include <math.h>
#include <stdint.h>

// ---------------- problem dims ----------------
constexpr int Bb = 32, Cc = 512, Hh = 24, Ww = 24;
constexpr int Ll = Hh * Ww;          // 576
constexpr int Dd = 1024, Kk = 4, Nst = 4, Rr = 32, MH = 2048;
constexpr int BL = Bb * Ll;          // 18432
constexpr int XDP = 256;             // padded x_proj output stride (160 used)

// ---------------- fp32 scratch ----------------
constexpr size_t OFF_XT     = 0;
constexpr size_t OFF_XDBL   = OFF_XT     + (size_t)BL * Cc;      // xd_pad [BL,256]
constexpr size_t OFF_XRES   = OFF_XDBL   + (size_t)BL * XDP;
constexpr size_t OFF_XFIN   = OFF_XRES   + (size_t)BL * Cc;
constexpr size_t OFF_DTWT   = OFF_XFIN   + (size_t)BL * Cc;
constexpr size_t OFF_CONVWT = OFF_DTWT   + (size_t)Kk * Rr * Dd;
constexpr size_t TOTF       = OFF_CONVWT + (size_t)9 * Dd;

__device__ __align__(128) float g_buf[TOTF];
#define BUF(off) (g_buf + (off))

// ---------------- fp16 scratch ----------------
constexpr size_t HH_H      = 0;
constexpr size_t HH_XZ     = HH_H      + (size_t)BL * Cc;
constexpr size_t HH_XC     = HH_XZ     + (size_t)BL * 2 * Dd;
constexpr size_t HH_DTS    = HH_XC     + (size_t)BL * Dd;
constexpr size_t HH_YS     = HH_DTS    + (size_t)Kk * BL * Dd;
constexpr size_t HH_YG     = HH_YS     + (size_t)Kk * BL * Dd;
constexpr size_t HH_M1     = HH_YG     + (size_t)BL * Dd;
constexpr size_t HH_MH     = HH_M1     + (size_t)BL * Cc;
constexpr size_t HH_WIP    = HH_MH     + (size_t)BL * MH;
constexpr size_t HH_WOP    = HH_WIP    + (size_t)2 * Dd * Cc;
constexpr size_t HH_WF1    = HH_WOP    + (size_t)Cc * Dd;
constexpr size_t HH_WF2    = HH_WF1    + (size_t)MH * Cc;
constexpr size_t HH_WXP_HI = HH_WF2    + (size_t)Cc * MH;
constexpr size_t HH_WXP_LO = HH_WXP_HI + (size_t)XDP * Dd;
constexpr size_t TOTH      = HH_WXP_LO + (size_t)XDP * Dd;

__device__ __align__(128) __half g_hh[TOTH];

// ---------------- helpers ----------------
__device__ __forceinline__ uint32_t s2u(const void* p) {
    uint32_t a;
    asm("{ .reg .u64 t; cvta.to.shared.u64 t, %1; cvt.u32.u64 %0, t; }" : "=r"(a) : "l"(p));
    return a;
}
__device__ __forceinline__ void cpasync16(uint32_t dst, const void* src) {
    asm volatile("cp.async.cg.shared.global [%0], [%1], 16;" :: "r"(dst), "l"(src));
}
__device__ __forceinline__ void cpcommit() { asm volatile("cp.async.commit_group;" ::: "memory"); }
__device__ __forceinline__ void cpwait2() { asm volatile("cp.async.wait_group 2;" ::: "memory"); }
__device__ __forceinline__ void ldm_x4(uint32_t* d, uint32_t addr) {
    asm volatile("ldmatrix.sync.aligned.m8n8.x4.shared.b16 {%0,%1,%2,%3}, [%4];"
                 : "=r"(d[0]), "=r"(d[1]), "=r"(d[2]), "=r"(d[3]) : "r"(addr));
}
__device__ __forceinline__ void ldm_x2(uint32_t* d, uint32_t addr) {
    asm volatile("ldmatrix.sync.aligned.m8n8.x2.shared.b16 {%0,%1}, [%2];"
                 : "=r"(d[0]), "=r"(d[1]) : "r"(addr));
}
__device__ __forceinline__ void mma_f16(float* c, const uint32_t* a, const uint32_t* b) {
    asm volatile(
        "mma.sync.aligned.m16n8k16.row.col.f32.f16.f16.f32 "
        "{%0,%1,%2,%3}, {%4,%5,%6,%7}, {%8,%9}, {%0,%1,%2,%3};"
        : "+f"(c[0]), "+f"(c[1]), "+f"(c[2]), "+f"(c[3])
        : "r"(a[0]), "r"(a[1]), "r"(a[2]), "r"(a[3]), "r"(b[0]), "r"(b[1]));
}
__device__ __forceinline__ float gelu_tanh(float x) {
    return 0.5f * x * (1.f + tanhf(0.7978845608028654f * (x + 0.044715f * x * x * x)));
}
__device__ __forceinline__ int permL(int k, int l) {
    int ll = (k & 2) ? (Ll - 1 - l) : l;
    if (k & 1) ll = (ll % Hh) * Ww + (ll / Hh);
    return ll;
}

// ---------------- fp16 tensor-core GEMM: C[M,N] = A @ (sum_p B_p)^T ----------------
// NP passes over B pointers (1 = plain fp16 weights, 2 = hi/lo split), fp32 accum.
// EPI 0: +bias -> fp32. EPI 1: +bias +res -> fp32. EPI 2: gelu(+bias) -> fp16. EPI 3: +bias -> fp16.
constexpr int GEMM_SMEM = 4 * 16384;   // 4 stages x (A 8KB + B 8KB)

template <int EPI, int NP>
__global__ __launch_bounds__(256)
void k_gemm_mma(const __half* __restrict__ A,
                const __half* __restrict__ Bhi, const __half* __restrict__ Blo,
                const float* __restrict__ bias, const float* __restrict__ res,
                float* __restrict__ outF, __half* __restrict__ outH,
                int Nn, int Kd) {
    extern __shared__ __align__(128) char sm[];
    const int tid = threadIdx.x, lane = tid & 31, wid = tid >> 5;
    const int wm = wid & 1, wn = wid >> 1;
    const int bm = blockIdx.x * 128, bn = blockIdx.y * 128;
    const int nk = Kd >> 5, T = NP * nk;
    const __half* pb[2] = {Bhi, Blo};

    const int rr = tid >> 2, cc = tid & 3;
    const uint32_t swLo = rr * 64 + (((cc + (rr >> 1)) & 3) << 4);
    const uint32_t swHi = (rr + 64) * 64 + (((cc + (rr >> 1)) & 3) << 4);
    const uint32_t smBase = s2u(sm);

    auto issue = [&](int it) {
        const int p = (NP == 2) ? (it >= nk) : 0;
        const int kc = (it - p * nk) * 32;
        const uint32_t st = smBase + (uint32_t)(it & 3) * 16384;
        const __half* Bp = pb[p];
        cpasync16(st + swLo,        A  + (size_t)(bm + rr)      * Kd + kc + cc * 8);
        cpasync16(st + swHi,        A  + (size_t)(bm + rr + 64) * Kd + kc + cc * 8);
        cpasync16(st + 8192 + swLo, Bp + (size_t)(bn + rr)      * Kd + kc + cc * 8);
        cpasync16(st + 8192 + swHi, Bp + (size_t)(bn + rr + 64) * Kd + kc + cc * 8);
    };

    float acc[4][4][4];
#pragma unroll
    for (int i = 0; i < 4; i++)
#pragma unroll
        for (int j = 0; j < 4; j++)
#pragma unroll
            for (int q = 0; q < 4; q++) acc[i][j][q] = 0.f;

    issue(0); cpcommit();
    issue(1); cpcommit();
    issue(2); cpcommit();

    for (int it = 0; it < T; it++) {
        cpwait2();
        __syncthreads();
        if (it + 3 < T) issue(it + 3);
        cpcommit();
        const uint32_t aB = smBase + (uint32_t)(it & 3) * 16384;
        const uint32_t bB = aB + 8192;
#pragma unroll
        for (int s16 = 0; s16 < 2; s16++) {
            uint32_t af[4][4], bfr[4][2];
#pragma unroll
            for (int mi = 0; mi < 4; mi++) {
                const int r = wm * 64 + mi * 16 + (lane & 15);
                const int c = 2 * s16 + (lane >> 4);
                ldm_x4(af[mi], aB + r * 64 + (((c + (r >> 1)) & 3) << 4));
            }
#pragma unroll
            for (int ni = 0; ni < 4; ni++) {
                const int i = lane & 15;
                const int r = wn * 32 + ni * 8 + (i & 7);
                const int c = 2 * s16 + (i >> 3);
                ldm_x2(bfr[ni], bB + r * 64 + (((c + (r >> 1)) & 3) << 4));
            }
#pragma unroll
            for (int mi = 0; mi < 4; mi++)
#pragma unroll
                for (int ni = 0; ni < 4; ni++)
                    mma_f16(acc[mi][ni], af[mi], bfr[ni]);
        }
    }

    // epilogue
#pragma unroll
    for (int mi = 0; mi < 4; mi++) {
#pragma unroll
        for (int ni = 0; ni < 4; ni++) {
            const int n = bn + wn * 32 + ni * 8 + (lane & 3) * 2;
            const float b0v = bias ? __ldg(bias + n) : 0.f;
            const float b1v = bias ? __ldg(bias + n + 1) : 0.f;
#pragma unroll
            for (int h = 0; h < 2; h++) {
                const int m = bm + wm * 64 + mi * 16 + (lane >> 2) + h * 8;
                float v0 = acc[mi][ni][h * 2 + 0] + b0v;
                float v1 = acc[mi][ni][h * 2 + 1] + b1v;
                if (EPI == 1) {
                    const float2 rv = *(const float2*)(res + (size_t)m * Nn + n);
                    v0 += rv.x; v1 += rv.y;
                }
                if (EPI == 2 || EPI == 3) {
                    if (EPI == 2) { v0 = gelu_tanh(v0); v1 = gelu_tanh(v1); }
                    __half2 hp; hp.x = __float2half(v0); hp.y = __float2half(v1);
                    *(__half2*)(outH + (size_t)m * Nn + n) = hp;
                } else {
                    *(float2*)(outF + (size_t)m * Nn + n) = make_float2(v0, v1);
                }
            }
        }
    }
}

// ---------------- xt = p2t(x1)+p2t(x2)+p2t(x3) ----------------
__global__ void k_fuse(const float* __restrict__ x1, const float* __restrict__ x2,
                       const float* __restrict__ x3) {
    __shared__ float t[32][33];
    const int b  = blockIdx.z;
    const int c0 = blockIdx.x * 32;
    const int l0 = blockIdx.y * 32;
    const int tx = threadIdx.x, ty = threadIdx.y;
    const size_t base = (size_t)b * Cc * Ll;
    for (int i = ty; i < 32; i += 8) {
        const size_t idx = base + (size_t)(c0 + i) * Ll + (l0 + tx);
        t[i][tx] = x1[idx] + x2[idx] + x3[idx];
    }
    __syncthreads();
    float* xt = BUF(OFF_XT);
    for (int i = ty; i < 32; i += 8)
        xt[((size_t)b * Ll + (l0 + i)) * Cc + (c0 + tx)] = t[tx][i];
}

// ---------------- LayerNorm(512) -> fp16 ----------------
__global__ void k_ln_h(const float* __restrict__ in, const float* __restrict__ w,
                       const float* __restrict__ bvec, __half* __restrict__ ho) {
    constexpr int T = 256;
    __shared__ float red[T];
    const size_t row = blockIdx.x;
    const float* x = in + row * Cc;
    const int tid = threadIdx.x;

    const float a0 = x[tid], a1 = x[tid + 256];
    red[tid] = a0 + a1; __syncthreads();
    for (int o = T / 2; o > 0; o >>= 1) { if (tid < o) red[tid] += red[tid + o]; __syncthreads(); }
    const float mu = red[0] * (1.f / Cc);
    __syncthreads();
    const float d0 = a0 - mu, d1 = a1 - mu;
    red[tid] = d0 * d0 + d1 * d1; __syncthreads();
    for (int o = T / 2; o > 0; o >>= 1) { if (tid < o) red[tid] += red[tid + o]; __syncthreads(); }
    const float inv = rsqrtf(red[0] * (1.f / Cc) + 1e-5f);

    ho[row * Cc + tid]       = __float2half((a0 - mu) * inv * w[tid] + bvec[tid]);
    ho[row * Cc + tid + 256] = __float2half((a1 - mu) * inv * w[tid + 256] + bvec[tid + 256]);
}

// ---------------- fp32 -> fp16 weight convert ----------------
__global__ void k_tofp16(const float* __restrict__ src, __half* __restrict__ dst, int n) {
    const int i = blockIdx.x * 256 + threadIdx.x;
    if (i < n) dst[i] = __float2half(src[i]);
}

// ---------------- x_proj weight: [160,1024] -> padded [256,1024] hi/lo split ----------------
__global__ void k_split_xp(const float* __restrict__ src, __half* __restrict__ hi,
                           __half* __restrict__ lo) {
    const int i = blockIdx.x * 256 + threadIdx.x;  // over 256*1024
    const int row = i >> 10;
    if (row < 160) {
        const float v = src[i - ((row - row) << 10) - 0 + 0];  // src[row*1024 + d] == src[i]
        const __half h = __float2half(src[i]);
        hi[i] = h;
        lo[i] = __float2half(src[i] - __half2float(h));
    } else {
        hi[i] = __float2half(0.f);
        lo[i] = __float2half(0.f);
    }
}

// ---------------- prep: dt_w (K,D,R)->(K,R,D), conv_w (D,9)->(9,D) ----------------
__global__ void k_prep(const float* __restrict__ dt_w, const float* __restrict__ conv_w) {
    const int i = blockIdx.x * 256 + threadIdx.x;
    if (i < Kk * Rr * Dd) {
        const int k = i / (Rr * Dd);
        const int rem = i % (Rr * Dd);
        const int r = rem / Dd, d = rem % Dd;
        BUF(OFF_DTWT)[i] = dt_w[((size_t)k * Dd + d) * Rr + r];
    }
    if (i < 9 * Dd) {
        const int j = i / Dd, d = i % Dd;
        BUF(OFF_CONVWT)[i] = conv_w[(size_t)d * 9 + j];
    }
}

// ---------------- depthwise 3x3 conv + SiLU (fp16 in/out, fp32 math) ----------------
__global__ void k_conv(const float* __restrict__ conv_b, const __half* __restrict__ xz,
                       __half* __restrict__ xc) {
    const int bl = blockIdx.x;
    const int d = blockIdx.y * 256 + threadIdx.x;
    const int b = bl / Ll, l = bl % Ll;
    const int h = l / Ww, w = l % Ww;
    const float* cw = BUF(OFF_CONVWT);
    float acc = 0.f;
#pragma unroll
    for (int kh = -1; kh <= 1; kh++) {
        const int hh = h + kh;
        if (hh < 0 || hh >= Hh) continue;
#pragma unroll
        for (int kw = -1; kw <= 1; kw++) {
            const int ww2 = w + kw;
            if (ww2 < 0 || ww2 >= Ww) continue;
            acc += __half2float(xz[((size_t)(b * Ll + hh * Ww + ww2)) * 2 * Dd + d]) *
                   cw[(size_t)((kh + 1) * 3 + (kw + 1)) * Dd + d];
        }
    }
    acc += conv_b[d];
    xc[(size_t)bl * Dd + d] = __float2half(acc / (1.f + __expf(-acc)));
}

// ---------------- dts = softplus(xd_r @ dt_w^T + dt_b) -> fp16 ----------------
__global__ void k_dt(const float* __restrict__ dt_b, __half* __restrict__ dts) {
    constexpr int LT = 8;
    __shared__ float s[LT][Rr];
    const int blk = blockIdx.x;
    const int lt = blk % (Ll / LT);
    const int rem = blk / (Ll / LT);
    const int b = rem % Bb;
    const int k = rem / Bb;
    const int l0 = lt * LT;
    const int tid = threadIdx.x;
    {
        const int i = tid / Rr, r = tid % Rr;
        const int pl = permL(k, l0 + i);
        s[i][r] = BUF(OFF_XDBL)[((size_t)b * Ll + pl) * XDP + k * 40 + r];
    }
    __syncthreads();
    const float* wT = BUF(OFF_DTWT);
    for (int dc = 0; dc < Dd / 256; dc++) {
        const int d = dc * 256 + tid;
        const float bias = dt_b[k * Dd + d];
        float acc[LT];
#pragma unroll
        for (int i = 0; i < LT; i++) acc[i] = bias;
        for (int r = 0; r < Rr; r++) {
            const float wv = wT[((size_t)k * Rr + r) * Dd + d];
#pragma unroll
            for (int i = 0; i < LT; i++) acc[i] += s[i][r] * wv;
        }
#pragma unroll
        for (int i = 0; i < LT; i++) {
            const float x = acc[i];
            const float sp = (x > 20.f) ? x : log1pf(__expf(x));
            dts[(((size_t)k * Bb + b) * Ll + l0 + i) * Dd + d] = __float2half(sp);
        }
    }
}

// ---------------- selective scan (fp16 u/dt/ys, fp32 state) ----------------
__global__ void k_scan(const float* __restrict__ A_logs, const float* __restrict__ Ds,
                       const __half* __restrict__ xcg, const __half* __restrict__ dtsg,
                       __half* __restrict__ ysg) {
    const int blk = blockIdx.x;
    const int dc = blk & 3;
    const int kb = blk >> 2;
    const int b = kb % Bb;
    const int k = kb / Bb;
    const int d = dc * 256 + threadIdx.x;

    float Aa[Nst];
#pragma unroll
    for (int n = 0; n < Nst; n++) Aa[n] = -__expf(A_logs[((size_t)k * Dd + d) * Nst + n]);
    const float Dv = Ds[k * Dd + d];

    const __half* xc = xcg + (size_t)b * Ll * Dd + d;
    const __half* dts = dtsg + ((size_t)k * Bb + b) * Ll * Dd + d;
    const float* xd = BUF(OFF_XDBL) + (size_t)b * Ll * XDP + k * 40 + Rr;
    __half* ys = ysg + ((size_t)k * Bb + b) * Ll * Dd + d;

    float hst[Nst] = {0.f, 0.f, 0.f, 0.f};
    for (int l = 0; l < Ll; l++) {
        const int pl = permL(k, l);
        const float u = __half2float(xc[(size_t)pl * Dd]);
        const float dt = __half2float(dts[(size_t)l * Dd]);
        const float* bc = xd + (size_t)pl * XDP;
        const float du = dt * u;
        float y = 0.f;
#pragma unroll
        for (int n = 0; n < Nst; n++) {
            const float dA = __expf(dt * Aa[n]);
            hst[n] = hst[n] * dA + du * bc[n];
            y += hst[n] * bc[Nst + n];
        }
        ys[(size_t)l * Dd] = __float2half(y + Dv * u);
    }
}

// ---------------- cross-merge + out_norm LN + SiLU(z) gate -> fp16 ----------------
__global__ void k_merge(const float* __restrict__ onw, const float* __restrict__ onb,
                        const __half* __restrict__ ys, const __half* __restrict__ xz,
                        __half* __restrict__ yg) {
    constexpr int T = 256;
    __shared__ float bufr[Dd];
    __shared__ float red[T];
    const int bl = blockIdx.x;
    const int b = bl / Ll, l = bl % Ll;
    const int h = l / Ww, w = l % Ww;
    const int lt = w * Hh + h;
    const int tid = threadIdx.x;

    const size_t r0 = (((size_t)(0 * Bb + b)) * Ll + l) * Dd;
    const size_t r1 = (((size_t)(1 * Bb + b)) * Ll + lt) * Dd;
    const size_t r2 = (((size_t)(2 * Bb + b)) * Ll + (Ll - 1 - l)) * Dd;
    const size_t r3 = (((size_t)(3 * Bb + b)) * Ll + (Ll - 1 - lt)) * Dd;

    float s = 0.f;
#pragma unroll
    for (int it = 0; it < Dd / T; it++) {
        const int d = tid + it * T;
        const float v = __half2float(ys[r0 + d]) + __half2float(ys[r1 + d]) +
                        __half2float(ys[r2 + d]) + __half2float(ys[r3 + d]);
        bufr[d] = v; s += v;
    }
    red[tid] = s; __syncthreads();
    for (int o = T / 2; o > 0; o >>= 1) { if (tid < o) red[tid] += red[tid + o]; __syncthreads(); }
    const float mu = red[0] * (1.f / Dd);
    __syncthreads();
    float s2 = 0.f;
#pragma unroll
    for (int it = 0; it < Dd / T; it++) {
        const int d = tid + it * T;
        const float dv = bufr[d] - mu; s2 += dv * dv;
    }
    red[tid] = s2; __syncthreads();
    for (int o = T / 2; o > 0; o >>= 1) { if (tid < o) red[tid] += red[tid + o]; __syncthreads(); }
    const float inv = rsqrtf(red[0] * (1.f / Dd) + 1e-5f);

#pragma unroll
    for (int it = 0; it < Dd / T; it++) {
        const int d = tid + it * T;
        const float zv = __half2float(xz[(size_t)bl * 2 * Dd + Dd + d]);
        const float g = zv / (1.f + __expf(-zv));
        yg[(size_t)bl * Dd + d] = __float2half(((bufr[d] - mu) * inv * onw[d] + onb[d]) * g);
    }
}

// ---------------- final token2patch transpose ----------------
__global__ void k_out(float* __restrict__ out) {
    __shared__ float t[32][33];
    const int b = blockIdx.z;
    const int l0 = blockIdx.x * 32;
    const int c0 = blockIdx.y * 32;
    const int tx = threadIdx.x, ty = threadIdx.y;
    const float* xf = BUF(OFF_XFIN);
    for (int i = ty; i < 32; i += 8)
        t[i][tx] = xf[((size_t)b * Ll + (l0 + i)) * Cc + (c0 + tx)];
    __syncthreads();
    for (int i = ty; i < 32; i += 8)
        out[((size_t)b * Cc + (c0 + i)) * Ll + (l0 + tx)] = t[tx][i];
}

// ---------------- launch ----------------
extern "C" void kernel_launch(void* const* d_in, const int* in_sizes, int n_in,
                              void* d_out, int out_size) {
    const float* x1        = (const float*)d_in[0];
    const float* x2        = (const float*)d_in[1];
    const float* x3        = (const float*)d_in[2];
    const float* ln1_w     = (const float*)d_in[3];
    const float* ln1_b     = (const float*)d_in[4];
    const float* in_proj_w = (const float*)d_in[5];
    const float* in_proj_b = (const float*)d_in[6];
    const float* conv_w    = (const float*)d_in[7];
    const float* conv_b    = (const float*)d_in[8];
    const float* x_proj_w  = (const float*)d_in[9];
    const float* dt_w      = (const float*)d_in[10];
    const float* dt_b      = (const float*)d_in[11];
    const float* A_logs    = (const float*)d_in[12];
    const float* Ds        = (const float*)d_in[13];
    const float* out_norm_w= (const float*)d_in[14];
    const float* out_norm_b= (const float*)d_in[15];
    const float* out_proj_w= (const float*)d_in[16];
    const float* out_proj_b= (const float*)d_in[17];
    const float* ln2_w     = (const float*)d_in[18];
    const float* ln2_b     = (const float*)d_in[19];
    const float* fc1_w     = (const float*)d_in[20];
    const float* fc1_b     = (const float*)d_in[21];
    const float* fc2_w     = (const float*)d_in[22];
    const float* fc2_b     = (const float*)d_in[23];
    float* out = (float*)d_out;

    void* pf = nullptr;  cudaGetSymbolAddress(&pf, g_buf);
    void* ph = nullptr;  cudaGetSymbolAddress(&ph, g_hh);
    float* F = (float*)pf;
    __half* HB = (__half*)ph;

    static bool attr_done = false;
    if (!attr_done) {
        cudaFuncSetAttribute(k_gemm_mma<0, 2>, cudaFuncAttributeMaxDynamicSharedMemorySize, GEMM_SMEM);
        cudaFuncSetAttribute(k_gemm_mma<1, 1>, cudaFuncAttributeMaxDynamicSharedMemorySize, GEMM_SMEM);
        cudaFuncSetAttribute(k_gemm_mma<2, 1>, cudaFuncAttributeMaxDynamicSharedMemorySize, GEMM_SMEM);
        cudaFuncSetAttribute(k_gemm_mma<3, 1>, cudaFuncAttributeMaxDynamicSharedMemorySize, GEMM_SMEM);
        attr_done = true;
    }

    // 1. fuse + transpose -> xt
    k_fuse<<<dim3(Cc / 32, Ll / 32, Bb), dim3(32, 8)>>>(x1, x2, x3);
    // 2. weight conversions
    k_tofp16<<<(2 * Dd * Cc + 255) / 256, 256>>>(in_proj_w, HB + HH_WIP, 2 * Dd * Cc);
    k_tofp16<<<(Cc * Dd + 255) / 256, 256>>>(out_proj_w, HB + HH_WOP, Cc * Dd);
    k_tofp16<<<(MH * Cc + 255) / 256, 256>>>(fc1_w, HB + HH_WF1, MH * Cc);
    k_tofp16<<<(Cc * MH + 255) / 256, 256>>>(fc2_w, HB + HH_WF2, Cc * MH);
    k_split_xp<<<(XDP * Dd) / 256, 256>>>(x_proj_w, HB + HH_WXP_HI, HB + HH_WXP_LO);
    k_prep<<<(Kk * Rr * Dd + 255) / 256, 256>>>(dt_w, conv_w);
    // 3. LN1 -> fp16
    k_ln_h<<<BL, 256>>>(F + OFF_XT, ln1_w, ln1_b, HB + HH_H);
    // 4. in_proj -> xz fp16
    k_gemm_mma<3, 1><<<dim3(BL / 128, 2 * Dd / 128), 256, GEMM_SMEM>>>(
        HB + HH_H, HB + HH_WIP, nullptr, in_proj_b, nullptr,
        nullptr, HB + HH_XZ, 2 * Dd, Cc);
    // 5. conv + silu -> xc fp16
    k_conv<<<dim3(BL, Dd / 256), 256>>>(conv_b, HB + HH_XZ, HB + HH_XC);
    // 6. x_proj (2-pass split) -> xd_pad fp32 [BL,256]
    k_gemm_mma<0, 2><<<dim3(BL / 128, XDP / 128), 256, GEMM_SMEM>>>(
        HB + HH_XC, HB + HH_WXP_HI, HB + HH_WXP_LO, nullptr, nullptr,
        F + OFF_XDBL, nullptr, XDP, Dd);
    // 7. dt projection + softplus -> dts fp16
    k_dt<<<Kk * Bb * (Ll / 8), 256>>>(dt_b, HB + HH_DTS);
    // 8. selective scan -> ys fp16
    k_scan<<<Kk * Bb * 4, 256>>>(A_logs, Ds, HB + HH_XC, HB + HH_DTS, HB + HH_YS);
    // 9. merge + LN + gate -> yg fp16
    k_merge<<<BL, 256>>>(out_norm_w, out_norm_b, HB + HH_YS, HB + HH_XZ, HB + HH_YG);
    // 10. out_proj + residual(xt) -> xres fp32
    k_gemm_mma<1, 1><<<dim3(BL / 128, Cc / 128), 256, GEMM_SMEM>>>(
        HB + HH_YG, HB + HH_WOP, nullptr, out_proj_b, F + OFF_XT,
        F + OFF_XRES, nullptr, Cc, Dd);
    // 11. LN2 -> fp16
    k_ln_h<<<BL, 256>>>(F + OFF_XRES, ln2_w, ln2_b, HB + HH_M1);
    // 12. fc1 + gelu -> mh fp16
    k_gemm_mma<2, 1><<<dim3(BL / 128, MH / 128), 256, GEMM_SMEM>>>(
        HB + HH_M1, HB + HH_WF1, nullptr, fc1_b, nullptr,
        nullptr, HB + HH_MH, MH, Cc);
    // 13. fc2 + residual(xres) -> xfin fp32
    k_gemm_mma<1, 1><<<dim3(BL / 128, Cc / 128), 256, GEMM_SMEM>>>(
        HB + HH_MH, HB + HH_WF2, nullptr, fc2_b, F + OFF_XRES,
        F + OFF_XFIN, nullptr, Cc, MH);
    // 14. token2patch
    k_out<<<dim3(Ll / 32, Cc / 32, Bb), dim3(32, 8)>>>(out);
}